// round 6
// baseline (speedup 1.0000x reference)
#include <cuda_runtime.h>
#include <cuda_bf16.h>
#include <cstdint>
#include <cstddef>

// ---------------- problem constants ------------------------------------------
#define BSZ  8
#define LEN  4096
#define HD   512
#define PD   256
#define MM   (BSZ * LEN)   // 32768
#define KD   512           // GEMM K (both GEMMs)
#define ND   512           // GEMM N (both GEMMs)
#define NCH  64            // scan chunks per sequence
#define CLEN 64            // chunk length (NCH*CLEN == LEN)
#define NTILES 1024        // (MM/128) * (ND/128)
#define GRID_P 296         // persistent CTAs (148 SMs * 2)

// ---------------- device scratch ---------------------------------------------
__device__ __align__(128) __nv_bfloat16 d_xhi[(size_t)MM * KD];     // 32 MB
__device__ __align__(128) __nv_bfloat16 d_xlo[(size_t)MM * KD];     // 32 MB
__device__ __align__(128) __nv_bfloat16 d_xshi[(size_t)MM * KD];    // 32 MB
__device__ __align__(128) __nv_bfloat16 d_xslo[(size_t)MM * KD];    // 32 MB
__device__ __align__(128) float         d_Bu[(size_t)MM * ND];      // 64 MB
__device__ __align__(128) __nv_bfloat16 d_W1t_hi[ND * KD];          // [n=2p+j][k=h]
__device__ __align__(128) __nv_bfloat16 d_W1t_lo[ND * KD];
__device__ __align__(128) __nv_bfloat16 d_W2t_hi[ND * KD];          // [n=h][k=2p+j]
__device__ __align__(128) __nv_bfloat16 d_W2t_lo[ND * KD];
__device__ float2 d_Lb[PD];
__device__ float2 d_gamma[PD];
__device__ float2 d_Ach[PD];
__device__ float2 d_fin[BSZ * NCH * PD];
__device__ float2 d_carry[BSZ * NCH * PD];

// ---------------- helpers ------------------------------------------------------
__device__ __forceinline__ uint32_t smem_u32(const void* p) {
    uint32_t a;
    asm("{ .reg .u64 t; cvta.to.shared.u64 t, %1; cvt.u32.u64 %0, t; }" : "=r"(a) : "l"(p));
    return a;
}
__device__ __forceinline__ uint32_t swz128(uint32_t o) { return o ^ ((o >> 3) & 0x70); }

__device__ __forceinline__ void cp16(uint32_t s, const void* g) {
    asm volatile("cp.async.cg.shared.global [%0], [%1], 16;" :: "r"(s), "l"(g) : "memory");
}
#define CP_COMMIT() asm volatile("cp.async.commit_group;" ::: "memory")
#define CP_WAIT1()  asm volatile("cp.async.wait_group 1;" ::: "memory")

__device__ __forceinline__ void ldsm4(uint32_t* r, uint32_t addr) {
    asm volatile("ldmatrix.sync.aligned.m8n8.x4.shared.b16 {%0,%1,%2,%3}, [%4];"
                 : "=r"(r[0]), "=r"(r[1]), "=r"(r[2]), "=r"(r[3]) : "r"(addr));
}
__device__ __forceinline__ void mma_bf16(float* d, const uint32_t* a, const uint32_t* b) {
    asm volatile(
        "mma.sync.aligned.m16n8k16.row.col.f32.bf16.bf16.f32 "
        "{%0,%1,%2,%3}, {%4,%5,%6,%7}, {%8,%9}, {%0,%1,%2,%3};"
        : "+f"(d[0]), "+f"(d[1]), "+f"(d[2]), "+f"(d[3])
        : "r"(a[0]), "r"(a[1]), "r"(a[2]), "r"(a[3]), "r"(b[0]), "r"(b[1]));
}
__device__ __forceinline__ void split1(float v, __nv_bfloat16& h, __nv_bfloat16& l) {
    h = __float2bfloat16_rn(v);
    l = __float2bfloat16_rn(v - __bfloat162float(h));
}

// ---------------- prep kernels ------------------------------------------------
__global__ void k_prep1(const float* __restrict__ Lre, const float* __restrict__ Lim,
                        const float* __restrict__ lstep) {
    int p = threadIdx.x;
    if (p < PD) {
        float step = expf(lstep[p]);
        float re = Lre[p], im = Lim[p];
        float er = expf(re * step);
        float sphi, cphi;
        sincosf(im * step, &sphi, &cphi);
        float2 Lb = make_float2(er * cphi, er * sphi);
        float nr = Lb.x - 1.0f, ni = Lb.y;
        float den = re * re + im * im;
        d_Lb[p] = Lb;
        d_gamma[p] = make_float2((nr * re + ni * im) / den, (ni * re - nr * im) / den);
        float2 a = Lb;
        #pragma unroll
        for (int i = 0; i < 6; i++) {   // Lb^64
            float ar = a.x * a.x - a.y * a.y;
            float ai = 2.0f * a.x * a.y;
            a = make_float2(ar, ai);
        }
        d_Ach[p] = a;
    }
}

__global__ void k_prep2(const float* __restrict__ Bin, const float* __restrict__ Cin) {
    int idx = blockIdx.x * blockDim.x + threadIdx.x;
    if (idx < PD * HD) {
        int p = idx / HD, h = idx % HD;
        float2 g = d_gamma[p];
        float br = Bin[(p * HD + h) * 2 + 0];
        float bi = Bin[(p * HD + h) * 2 + 1];
        float w1r = g.x * br - g.y * bi;   // n = 2p
        float w1i = g.x * bi + g.y * br;   // n = 2p+1
        __nv_bfloat16 hh, ll;
        split1(w1r, hh, ll); d_W1t_hi[(2 * p + 0) * KD + h] = hh; d_W1t_lo[(2 * p + 0) * KD + h] = ll;
        split1(w1i, hh, ll); d_W1t_hi[(2 * p + 1) * KD + h] = hh; d_W1t_lo[(2 * p + 1) * KD + h] = ll;
        float cr = Cin[(h * PD + p) * 2 + 0];
        float ci = Cin[(h * PD + p) * 2 + 1];
        split1( 2.0f * cr, hh, ll); d_W2t_hi[h * KD + 2 * p + 0] = hh; d_W2t_lo[h * KD + 2 * p + 0] = ll;
        split1(-2.0f * ci, hh, ll); d_W2t_hi[h * KD + 2 * p + 1] = hh; d_W2t_lo[h * KD + 2 * p + 1] = ll;
    }
}

__global__ void __launch_bounds__(256) k_split(const float* __restrict__ x) {
    size_t i = (size_t)blockIdx.x * 256 + threadIdx.x;
    float4 v = *(const float4*)(x + i * 4);
    __nv_bfloat16 h0, h1, h2, h3, l0, l1, l2, l3;
    split1(v.x, h0, l0); split1(v.y, h1, l1); split1(v.z, h2, l2); split1(v.w, h3, l3);
    __nv_bfloat162 hi01 = __halves2bfloat162(h0, h1), hi23 = __halves2bfloat162(h2, h3);
    __nv_bfloat162 lo01 = __halves2bfloat162(l0, l1), lo23 = __halves2bfloat162(l2, l3);
    ((uint2*)d_xhi)[i] = make_uint2(*(uint32_t*)&hi01, *(uint32_t*)&hi23);
    ((uint2*)d_xlo)[i] = make_uint2(*(uint32_t*)&lo01, *(uint32_t*)&lo23);
}

// ---------------- persistent HMMA GEMM -----------------------------------------
// 128x128 CTA tile, 8 warps (32x64 warp tile), K chunks of 64.
// smem: 3 stages x (A 16KB + B 16KB) = 96KB -> 2 CTAs/SM. Chunk ring runs
// continuously across tiles; cp.async issued in 4 quarters interleaved with ks.
#define CHK    64
#define STG_A(s)  ((s) * 16384u)
#define STG_B(s)  (49152u + (s) * 16384u)
#define GSM_TOTAL 98304

template <bool EPI>
__global__ void __launch_bounds__(256, 2)
gemm_hmma(const __nv_bfloat16* __restrict__ Ahi, const __nv_bfloat16* __restrict__ Alo,
          const __nv_bfloat16* __restrict__ Whi, const __nv_bfloat16* __restrict__ Wlo,
          float* __restrict__ Cout, const float* __restrict__ Xs, const float* __restrict__ Dv) {
    extern __shared__ char smem[];
    uint32_t sb = smem_u32(smem);
    const int tid = threadIdx.x, wid = tid >> 5, lane = tid & 31;
    const int wm = wid & 3, wn = wid >> 2;            // 4 x 2 warp grid
    const int GR = gridDim.x;

    const __nv_bfloat16* APASS[3] = {Ahi, Alo, Ahi};
    const __nv_bfloat16* BPASS[3] = {Whi, Whi, Wlo};

    // tile schedule for this CTA
    int ntiles = 0;
    for (int u = blockIdx.x; u < NTILES; u += GR) ntiles++;
    const int total = ntiles * 24;

    int t  = blockIdx.x;
    int m0 = (t >> 2) * 128, n0 = (t & 3) * 128;
    int tn = t + GR;
    int m0n = (tn >> 2) * 128, n0n = (tn & 3) * 128;

    // ldsm per-lane swizzled base offsets (XOR ks*32 later; bits disjoint)
    const uint32_t offA0 = swz128((wm * 32 + (lane & 15)) * 128 + (lane >> 4) * 16);
    const uint32_t offA1 = swz128((wm * 32 + 16 + (lane & 15)) * 128 + (lane >> 4) * 16);
    const int rowB = wn * 64 + ((lane >> 4) & 1) * 8 + (lane & 7);
    const uint32_t colB = ((lane >> 3) & 1) * 16;
    uint32_t offB[4];
    #pragma unroll
    for (int nt2 = 0; nt2 < 4; nt2++)
        offB[nt2] = swz128((rowB + nt2 * 16) * 128 + colB);

    // cp.async per-thread geometry: quarter q covers rows [q*32, q*32+32)
    const int cprow = tid >> 3;        // 0..31
    const int cpc16 = tid & 7;         // 16B column
    uint32_t cpdst[4];
    #pragma unroll
    for (int q = 0; q < 4; q++)
        cpdst[q] = swz128((cprow + q * 32) * 128 + cpc16 * 16);

    float acc[2][8][4];
    #pragma unroll
    for (int i = 0; i < 2; i++)
        #pragma unroll
        for (int j = 0; j < 8; j++)
            #pragma unroll
            for (int q = 0; q < 4; q++) acc[i][j][q] = 0.0f;

    // prologue: fully issue chunks 0 and 1 (both in first tile, pass 0)
    #pragma unroll
    for (int g = 0; g < 2; g++) {
        uint32_t ab = sb + STG_A(g), bb = sb + STG_B(g);
        int kc = g * CHK;
        #pragma unroll
        for (int q = 0; q < 4; q++) {
            int row = cprow + q * 32;
            cp16(ab + cpdst[q], Ahi + (size_t)(m0 + row) * KD + kc + cpc16 * 8);
            cp16(bb + cpdst[q], Whi + (size_t)(n0 + row) * KD + kc + cpc16 * 8);
        }
        CP_COMMIT();
    }

    int c = 0;        // chunk index within current tile (0..23)
    int st = 0;       // stage of current chunk
    for (int g = 0; g < total; g++) {
        CP_WAIT1();
        __syncthreads();

        // params of chunk g+2 (to be issued during this chunk's compute)
        const bool nvld = (g + 2) < total;
        int ci = c + 2;
        int nm0 = m0, nn0 = n0;
        if (ci >= 24) { ci -= 24; nm0 = m0n; nn0 = n0n; }
        const __nv_bfloat16* nA = APASS[ci >> 3];
        const __nv_bfloat16* nW = BPASS[ci >> 3];
        const int nkc = (ci & 7) * CHK;
        int stn = st + 2; if (stn >= 3) stn -= 3;
        const uint32_t nab = sb + STG_A(stn), nbb = sb + STG_B(stn);

        const uint32_t aB = sb + STG_A(st), bB = sb + STG_B(st);
        #pragma unroll
        for (int ks = 0; ks < 4; ks++) {
            const uint32_t kx = ks * 32;
            uint32_t afr[2][4], bfr[4][4];
            ldsm4(afr[0], aB + (offA0 ^ kx));
            ldsm4(afr[1], aB + (offA1 ^ kx));
            #pragma unroll
            for (int nt2 = 0; nt2 < 4; nt2++)
                ldsm4(bfr[nt2], bB + (offB[nt2] ^ kx));
            if (nvld) {   // interleave quarter ks of next chunk's loads
                int row = cprow + ks * 32;
                cp16(nab + cpdst[ks], nA + (size_t)(nm0 + row) * KD + nkc + cpc16 * 8);
                cp16(nbb + cpdst[ks], nW + (size_t)(nn0 + row) * KD + nkc + cpc16 * 8);
            }
            #pragma unroll
            for (int mt = 0; mt < 2; mt++)
                #pragma unroll
                for (int nt = 0; nt < 8; nt++)
                    mma_bf16(acc[mt][nt], afr[mt], &bfr[nt >> 1][(nt & 1) * 2]);
        }
        CP_COMMIT();   // one group per loop iteration (possibly empty)

        st++; if (st >= 3) st = 0;
        if (++c == 24) {
            // epilogue for tile (m0, n0); pure reg->gmem, overlaps in-flight loads
            const int gq = lane >> 2, tig = lane & 3;
            #pragma unroll
            for (int mt = 0; mt < 2; mt++) {
                #pragma unroll
                for (int nt = 0; nt < 8; nt++) {
                    int r0 = m0 + wm * 32 + mt * 16 + gq;
                    int cc = n0 + wn * 64 + nt * 8 + tig * 2;
                    float2 v0 = make_float2(acc[mt][nt][0], acc[mt][nt][1]);
                    float2 v1 = make_float2(acc[mt][nt][2], acc[mt][nt][3]);
                    if (EPI) {
                        float2 dv = *(const float2*)(Dv + cc);
                        float2 x0 = *(const float2*)(Xs + (size_t)r0 * ND + cc);
                        float2 x1 = *(const float2*)(Xs + (size_t)(r0 + 8) * ND + cc);
                        v0.x = fmaf(dv.x, x0.x, v0.x); v0.y = fmaf(dv.y, x0.y, v0.y);
                        v1.x = fmaf(dv.x, x1.x, v1.x); v1.y = fmaf(dv.y, x1.y, v1.y);
                    }
                    *(float2*)(Cout + (size_t)r0 * ND + cc) = v0;
                    *(float2*)(Cout + (size_t)(r0 + 8) * ND + cc) = v1;
                    acc[mt][nt][0] = 0.0f; acc[mt][nt][1] = 0.0f;
                    acc[mt][nt][2] = 0.0f; acc[mt][nt][3] = 0.0f;
                }
            }
            c = 0;
            t = tn; m0 = m0n; n0 = n0n;
            tn += GR; m0n = (tn >> 2) * 128; n0n = (tn & 3) * 128;
        }
    }
}

// ---------------- chunked complex scan ----------------------------------------
__global__ void __launch_bounds__(256) k_scan1() {
    int t = blockIdx.x * 256 + threadIdx.x;          // (b*NCH+ch)*PD + p
    int p = t & (PD - 1);
    float2 a = d_Lb[p];
    const float2* bu = (const float2*)d_Bu + (size_t)(t >> 8) * (CLEN * PD) + p;
    float2 s = make_float2(0.0f, 0.0f);
    #pragma unroll 4
    for (int l = 0; l < CLEN; l++) {
        float2 v = bu[(size_t)l * PD];
        float sr = fmaf(a.x, s.x, fmaf(-a.y, s.y, v.x));
        float si = fmaf(a.x, s.y, fmaf(a.y, s.x, v.y));
        s.x = sr; s.y = si;
    }
    d_fin[t] = s;
}

__global__ void __launch_bounds__(256) k_scan2() {
    int t = blockIdx.x * 256 + threadIdx.x;          // b*PD + p
    int p = t & (PD - 1);
    int b = t >> 8;
    float2 A = d_Ach[p];
    float2 c = make_float2(0.0f, 0.0f);
    for (int ch = 0; ch < NCH; ch++) {
        int idx = (b * NCH + ch) * PD + p;
        d_carry[idx] = c;
        float2 f = d_fin[idx];
        float cr = fmaf(A.x, c.x, fmaf(-A.y, c.y, f.x));
        float ci = fmaf(A.x, c.y, fmaf(A.y, c.x, f.y));
        c.x = cr; c.y = ci;
    }
}

__global__ void __launch_bounds__(256) k_scan3() {
    int t = blockIdx.x * 256 + threadIdx.x;
    int p = t & (PD - 1);
    float2 a = d_Lb[p];
    size_t mbase = (size_t)(t >> 8) * CLEN;
    const float2* bu = (const float2*)d_Bu + mbase * PD + p;
    float2 s = d_carry[t];
    #pragma unroll 4
    for (int l = 0; l < CLEN; l++) {
        float2 v = bu[(size_t)l * PD];
        float sr = fmaf(a.x, s.x, fmaf(-a.y, s.y, v.x));
        float si = fmaf(a.x, s.y, fmaf(a.y, s.x, v.y));
        s.x = sr; s.y = si;
        __nv_bfloat16 hr, lr, hi, li;
        split1(sr, hr, lr);
        split1(si, hi, li);
        size_t off = (mbase + l) * ND + 2 * p;
        __nv_bfloat162 hv = __halves2bfloat162(hr, hi);
        __nv_bfloat162 lv = __halves2bfloat162(lr, li);
        *(uint32_t*)(d_xshi + off) = *(uint32_t*)&hv;
        *(uint32_t*)(d_xslo + off) = *(uint32_t*)&lv;
    }
}

// ---------------- launch -------------------------------------------------------
extern "C" void kernel_launch(void* const* d_in, const int* in_sizes, int n_in,
                              void* d_out, int out_size) {
    const float* x   = (const float*)d_in[0];
    const float* Lre = (const float*)d_in[1];
    const float* Lim = (const float*)d_in[2];
    const float* Bin = (const float*)d_in[3];
    const float* Cin = (const float*)d_in[4];
    const float* Dv  = (const float*)d_in[5];
    const float* ls  = (const float*)d_in[6];
    float* out = (float*)d_out;

    __nv_bfloat16 *pxhi, *pxlo, *pxshi, *pxslo, *pW1h, *pW1l, *pW2h, *pW2l;
    float* pBu;
    cudaGetSymbolAddress((void**)&pxhi,  d_xhi);
    cudaGetSymbolAddress((void**)&pxlo,  d_xlo);
    cudaGetSymbolAddress((void**)&pxshi, d_xshi);
    cudaGetSymbolAddress((void**)&pxslo, d_xslo);
    cudaGetSymbolAddress((void**)&pW1h,  d_W1t_hi);
    cudaGetSymbolAddress((void**)&pW1l,  d_W1t_lo);
    cudaGetSymbolAddress((void**)&pW2h,  d_W2t_hi);
    cudaGetSymbolAddress((void**)&pW2l,  d_W2t_lo);
    cudaGetSymbolAddress((void**)&pBu,   d_Bu);

    cudaFuncSetAttribute(gemm_hmma<false>, cudaFuncAttributeMaxDynamicSharedMemorySize, GSM_TOTAL);
    cudaFuncSetAttribute(gemm_hmma<true>,  cudaFuncAttributeMaxDynamicSharedMemorySize, GSM_TOTAL);

    k_prep1<<<1, 256>>>(Lre, Lim, ls);
    k_prep2<<<(PD * HD + 255) / 256, 256>>>(Bin, Cin);
    k_split<<<(int)(((size_t)MM * KD / 4) / 256), 256>>>(x);

    gemm_hmma<false><<<GRID_P, 256, GSM_TOTAL>>>(pxhi, pxlo, pW1h, pW1l, pBu, nullptr, nullptr);

    k_scan1<<<(BSZ * NCH * PD) / 256, 256>>>();
    k_scan2<<<(BSZ * PD) / 256, 256>>>();
    k_scan3<<<(BSZ * NCH * PD) / 256, 256>>>();

    gemm_hmma<true><<<GRID_P, 256, GSM_TOTAL>>>(pxshi, pxslo, pW2h, pW2l, out, x, Dv);
}

// round 10
// speedup vs baseline: 1.0358x; 1.0358x over previous
#include <cuda_runtime.h>
#include <cuda_bf16.h>
#include <cstdint>
#include <cstddef>

// ---------------- problem constants ------------------------------------------
#define BSZ  8
#define LEN  4096
#define HD   512
#define PD   256
#define MM   (BSZ * LEN)   // 32768
#define KD   512           // GEMM K (both GEMMs)
#define ND   512           // GEMM N (both GEMMs)
#define NCH  64            // scan chunks per sequence
#define CLEN 64            // chunk length (NCH*CLEN == LEN)

// ---------------- device scratch ---------------------------------------------
__device__ __align__(128) __nv_bfloat16 d_xhi[(size_t)MM * KD];     // 32 MB
__device__ __align__(128) __nv_bfloat16 d_xlo[(size_t)MM * KD];     // 32 MB
__device__ __align__(128) __nv_bfloat16 d_xshi[(size_t)MM * KD];    // 32 MB
__device__ __align__(128) __nv_bfloat16 d_xslo[(size_t)MM * KD];    // 32 MB
__device__ __align__(128) float         d_Bu[(size_t)MM * ND];      // 64 MB
__device__ __align__(128) __nv_bfloat16 d_W1t_hi[ND * KD];          // [n=2p+j][k=h]
__device__ __align__(128) __nv_bfloat16 d_W1t_lo[ND * KD];
__device__ __align__(128) __nv_bfloat16 d_W2t_hi[ND * KD];          // [n=h][k=2p+j]
__device__ __align__(128) __nv_bfloat16 d_W2t_lo[ND * KD];
__device__ float2 d_Lb[PD];
__device__ float2 d_gamma[PD];
__device__ float2 d_Ach[PD];
__device__ float2 d_fin[BSZ * NCH * PD];
__device__ float2 d_carry[BSZ * NCH * PD];

// ---------------- helpers ------------------------------------------------------
__device__ __forceinline__ uint32_t smem_u32(const void* p) {
    uint32_t a;
    asm("{ .reg .u64 t; cvta.to.shared.u64 t, %1; cvt.u32.u64 %0, t; }" : "=r"(a) : "l"(p));
    return a;
}
__device__ __forceinline__ uint32_t swz128(uint32_t o) { return o ^ ((o >> 3) & 0x70); }

__device__ __forceinline__ void cp16(uint32_t s, const void* g) {
    asm volatile("cp.async.cg.shared.global [%0], [%1], 16;" :: "r"(s), "l"(g) : "memory");
}
#define CP_COMMIT() asm volatile("cp.async.commit_group;" ::: "memory")
#define CP_WAIT1()  asm volatile("cp.async.wait_group 1;" ::: "memory")
#define CP_WAIT0()  asm volatile("cp.async.wait_group 0;" ::: "memory")

__device__ __forceinline__ void ldsm4(uint32_t* r, uint32_t addr) {
    asm volatile("ldmatrix.sync.aligned.m8n8.x4.shared.b16 {%0,%1,%2,%3}, [%4];"
                 : "=r"(r[0]), "=r"(r[1]), "=r"(r[2]), "=r"(r[3]) : "r"(addr));
}
__device__ __forceinline__ void mma_bf16(float* d, const uint32_t* a, const uint32_t* b) {
    asm volatile(
        "mma.sync.aligned.m16n8k16.row.col.f32.bf16.bf16.f32 "
        "{%0,%1,%2,%3}, {%4,%5,%6,%7}, {%8,%9}, {%0,%1,%2,%3};"
        : "+f"(d[0]), "+f"(d[1]), "+f"(d[2]), "+f"(d[3])
        : "r"(a[0]), "r"(a[1]), "r"(a[2]), "r"(a[3]), "r"(b[0]), "r"(b[1]));
}
__device__ __forceinline__ void split1(float v, __nv_bfloat16& h, __nv_bfloat16& l) {
    h = __float2bfloat16_rn(v);
    l = __float2bfloat16_rn(v - __bfloat162float(h));
}

// ---------------- prep kernels ------------------------------------------------
__global__ void k_prep1(const float* __restrict__ Lre, const float* __restrict__ Lim,
                        const float* __restrict__ lstep) {
    int p = threadIdx.x;
    if (p < PD) {
        float step = expf(lstep[p]);
        float re = Lre[p], im = Lim[p];
        float er = expf(re * step);
        float sphi, cphi;
        sincosf(im * step, &sphi, &cphi);
        float2 Lb = make_float2(er * cphi, er * sphi);
        float nr = Lb.x - 1.0f, ni = Lb.y;
        float den = re * re + im * im;
        d_Lb[p] = Lb;
        d_gamma[p] = make_float2((nr * re + ni * im) / den, (ni * re - nr * im) / den);
        float2 a = Lb;
        #pragma unroll
        for (int i = 0; i < 6; i++) {   // Lb^64
            float ar = a.x * a.x - a.y * a.y;
            float ai = 2.0f * a.x * a.y;
            a = make_float2(ar, ai);
        }
        d_Ach[p] = a;
    }
}

__global__ void k_prep2(const float* __restrict__ Bin, const float* __restrict__ Cin) {
    int idx = blockIdx.x * blockDim.x + threadIdx.x;
    if (idx < PD * HD) {
        int p = idx / HD, h = idx % HD;
        float2 g = d_gamma[p];
        float br = Bin[(p * HD + h) * 2 + 0];
        float bi = Bin[(p * HD + h) * 2 + 1];
        float w1r = g.x * br - g.y * bi;   // n = 2p
        float w1i = g.x * bi + g.y * br;   // n = 2p+1
        __nv_bfloat16 hh, ll;
        split1(w1r, hh, ll); d_W1t_hi[(2 * p + 0) * KD + h] = hh; d_W1t_lo[(2 * p + 0) * KD + h] = ll;
        split1(w1i, hh, ll); d_W1t_hi[(2 * p + 1) * KD + h] = hh; d_W1t_lo[(2 * p + 1) * KD + h] = ll;
        float cr = Cin[(h * PD + p) * 2 + 0];
        float ci = Cin[(h * PD + p) * 2 + 1];
        split1( 2.0f * cr, hh, ll); d_W2t_hi[h * KD + 2 * p + 0] = hh; d_W2t_lo[h * KD + 2 * p + 0] = ll;
        split1(-2.0f * ci, hh, ll); d_W2t_hi[h * KD + 2 * p + 1] = hh; d_W2t_lo[h * KD + 2 * p + 1] = ll;
    }
}

__global__ void __launch_bounds__(256) k_split(const float* __restrict__ x) {
    size_t i = (size_t)blockIdx.x * 256 + threadIdx.x;
    float4 v = *(const float4*)(x + i * 4);
    __nv_bfloat16 h0, h1, h2, h3, l0, l1, l2, l3;
    split1(v.x, h0, l0); split1(v.y, h1, l1); split1(v.z, h2, l2); split1(v.w, h3, l3);
    __nv_bfloat162 hi01 = __halves2bfloat162(h0, h1), hi23 = __halves2bfloat162(h2, h3);
    __nv_bfloat162 lo01 = __halves2bfloat162(l0, l1), lo23 = __halves2bfloat162(l2, l3);
    ((uint2*)d_xhi)[i] = make_uint2(*(uint32_t*)&hi01, *(uint32_t*)&hi23);
    ((uint2*)d_xlo)[i] = make_uint2(*(uint32_t*)&lo01, *(uint32_t*)&lo23);
}

// ---------------- HMMA GEMM: 128x128 CTA, 8 warps (32x64 warp tile) -----------
// Superchunk: CHK=32 K-cols; each stage row = [hi 64B | lo 64B] (128B, SW128).
// One chunk holds Ahi|Alo and Whi|Wlo; computes 3 products (ahi*bhi, alo*bhi,
// ahi*blo) with ahi/bhi fragments reused in registers.
// smem: 3 stages x (A 16KB + B 16KB) = 96KB -> 2 CTAs/SM.
#define CHK    32
#define NC     16
#define STG_A(s)  ((s) * 16384u)
#define STG_B(s)  (49152u + (s) * 16384u)
#define GSM_TOTAL 98304

template <bool EPI>
__global__ void __launch_bounds__(256, 2)
gemm_hmma(const __nv_bfloat16* __restrict__ Ahi, const __nv_bfloat16* __restrict__ Alo,
          const __nv_bfloat16* __restrict__ Whi, const __nv_bfloat16* __restrict__ Wlo,
          float* __restrict__ Cout, const float* __restrict__ Xs, const float* __restrict__ Dv) {
    extern __shared__ char smem[];
    uint32_t sb = smem_u32(smem);
    const int tid = threadIdx.x, wid = tid >> 5, lane = tid & 31;
    const int wm = wid & 3, wn = wid >> 2;            // 4 x 2 warp grid
    const int m0 = blockIdx.y * 128, n0 = blockIdx.x * 128;

    // cp.async geometry: c16 = tid&7 fixed per thread; c16<4 -> hi half, else lo
    const int cprow0 = tid >> 3;               // 0..31 (+ i*32)
    const int cpc16  = tid & 7;
    const uint32_t cpcol = (uint32_t)cpc16 * 16;
    const __nv_bfloat16* Asrc = (cpc16 < 4) ? (Ahi + cpc16 * 8) : (Alo + (cpc16 - 4) * 8);
    const __nv_bfloat16* Wsrc = (cpc16 < 4) ? (Whi + cpc16 * 8) : (Wlo + (cpc16 - 4) * 8);

    // ldsm per-lane swizzled base offsets; XOR with ks*32 (bit5) / 64 (bit6)
    const uint32_t offA0 = swz128((wm * 32 + (lane & 15)) * 128 + (lane >> 4) * 16);
    const uint32_t offA1 = swz128((wm * 32 + 16 + (lane & 15)) * 128 + (lane >> 4) * 16);
    const int rowB = wn * 64 + ((lane >> 4) & 1) * 8 + (lane & 7);
    const uint32_t colB = ((lane >> 3) & 1) * 16;
    uint32_t offB[4];
    #pragma unroll
    for (int nt2 = 0; nt2 < 4; nt2++)
        offB[nt2] = swz128((rowB + nt2 * 16) * 128 + colB);

    float acc[2][8][4];
    #pragma unroll
    for (int i = 0; i < 2; i++)
        #pragma unroll
        for (int j = 0; j < 8; j++)
            #pragma unroll
            for (int q = 0; q < 4; q++) acc[i][j][q] = 0.0f;

    // prologue: issue chunks 0 and 1
    #pragma unroll
    for (int g = 0; g < 2; g++) {
        uint32_t ab = sb + STG_A(g), bb = sb + STG_B(g);
        int kc = g * CHK;
        #pragma unroll
        for (int i = 0; i < 4; i++) {
            int row = cprow0 + i * 32;
            uint32_t d = swz128(row * 128 + cpcol);
            cp16(ab + d, Asrc + (size_t)(m0 + row) * KD + kc);
            cp16(bb + d, Wsrc + (size_t)(n0 + row) * KD + kc);
        }
        CP_COMMIT();
    }

    for (int c = 0; c < NC; c++) {
        CP_WAIT1();
        __syncthreads();
        if (c + 2 < NC) {
            int cn = c + 2;
            uint32_t ab = sb + STG_A(cn % 3), bb = sb + STG_B(cn % 3);
            int kc = cn * CHK;
            #pragma unroll
            for (int i = 0; i < 4; i++) {
                int row = cprow0 + i * 32;
                uint32_t d = swz128(row * 128 + cpcol);
                cp16(ab + d, Asrc + (size_t)(m0 + row) * KD + kc);
                cp16(bb + d, Wsrc + (size_t)(n0 + row) * KD + kc);
            }
            CP_COMMIT();
        } else {
            CP_COMMIT();   // keep group accounting uniform
        }
        // compute stage c%3: 3 products per ks
        const uint32_t aB = sb + STG_A(c % 3), bB = sb + STG_B(c % 3);
        #pragma unroll
        for (int ks = 0; ks < 2; ks++) {
            const uint32_t kx = ks * 32;
            uint32_t ahi[2][4], alo[2][4], bhi[4][4], blo[4][4];
            ldsm4(ahi[0], aB + (offA0 ^ kx));
            ldsm4(ahi[1], aB + (offA1 ^ kx));
            #pragma unroll
            for (int nt2 = 0; nt2 < 4; nt2++)
                ldsm4(bhi[nt2], bB + (offB[nt2] ^ kx));
            #pragma unroll
            for (int mt = 0; mt < 2; mt++)
                #pragma unroll
                for (int nt = 0; nt < 8; nt++)
                    mma_bf16(acc[mt][nt], ahi[mt], &bhi[nt >> 1][(nt & 1) * 2]);
            ldsm4(alo[0], aB + (offA0 ^ kx ^ 64u));
            ldsm4(alo[1], aB + (offA1 ^ kx ^ 64u));
            #pragma unroll
            for (int mt = 0; mt < 2; mt++)
                #pragma unroll
                for (int nt = 0; nt < 8; nt++)
                    mma_bf16(acc[mt][nt], alo[mt], &bhi[nt >> 1][(nt & 1) * 2]);
            #pragma unroll
            for (int nt2 = 0; nt2 < 4; nt2++)
                ldsm4(blo[nt2], bB + (offB[nt2] ^ kx ^ 64u));
            #pragma unroll
            for (int mt = 0; mt < 2; mt++)
                #pragma unroll
                for (int nt = 0; nt < 8; nt++)
                    mma_bf16(acc[mt][nt], ahi[mt], &blo[nt >> 1][(nt & 1) * 2]);
        }
    }
    CP_WAIT0();

    // epilogue: d0,d1 -> (row g, col 2t..2t+1); d2,d3 -> row g+8
    const int g = lane >> 2, tig = lane & 3;
    #pragma unroll
    for (int mt = 0; mt < 2; mt++) {
        #pragma unroll
        for (int nt = 0; nt < 8; nt++) {
            int r0 = m0 + wm * 32 + mt * 16 + g;
            int cc = n0 + wn * 64 + nt * 8 + tig * 2;
            float2 v0 = make_float2(acc[mt][nt][0], acc[mt][nt][1]);
            float2 v1 = make_float2(acc[mt][nt][2], acc[mt][nt][3]);
            if (EPI) {
                float2 dv = *(const float2*)(Dv + cc);
                float2 x0 = *(const float2*)(Xs + (size_t)r0 * ND + cc);
                float2 x1 = *(const float2*)(Xs + (size_t)(r0 + 8) * ND + cc);
                v0.x = fmaf(dv.x, x0.x, v0.x); v0.y = fmaf(dv.y, x0.y, v0.y);
                v1.x = fmaf(dv.x, x1.x, v1.x); v1.y = fmaf(dv.y, x1.y, v1.y);
            }
            *(float2*)(Cout + (size_t)r0 * ND + cc) = v0;
            *(float2*)(Cout + (size_t)(r0 + 8) * ND + cc) = v1;
        }
    }
}

// ---------------- chunked complex scan ----------------------------------------
__global__ void __launch_bounds__(256) k_scan1() {
    int t = blockIdx.x * 256 + threadIdx.x;          // (b*NCH+ch)*PD + p
    int p = t & (PD - 1);
    float2 a = d_Lb[p];
    const float2* bu = (const float2*)d_Bu + (size_t)(t >> 8) * (CLEN * PD) + p;
    float2 s = make_float2(0.0f, 0.0f);
    #pragma unroll 4
    for (int l = 0; l < CLEN; l++) {
        float2 v = bu[(size_t)l * PD];
        float sr = fmaf(a.x, s.x, fmaf(-a.y, s.y, v.x));
        float si = fmaf(a.x, s.y, fmaf(a.y, s.x, v.y));
        s.x = sr; s.y = si;
    }
    d_fin[t] = s;
}

__global__ void __launch_bounds__(256) k_scan2() {
    int t = blockIdx.x * 256 + threadIdx.x;          // b*PD + p
    int p = t & (PD - 1);
    int b = t >> 8;
    float2 A = d_Ach[p];
    float2 c = make_float2(0.0f, 0.0f);
    for (int ch = 0; ch < NCH; ch++) {
        int idx = (b * NCH + ch) * PD + p;
        d_carry[idx] = c;
        float2 f = d_fin[idx];
        float cr = fmaf(A.x, c.x, fmaf(-A.y, c.y, f.x));
        float ci = fmaf(A.x, c.y, fmaf(A.y, c.x, f.y));
        c.x = cr; c.y = ci;
    }
}

__global__ void __launch_bounds__(256) k_scan3() {
    int t = blockIdx.x * 256 + threadIdx.x;
    int p = t & (PD - 1);
    float2 a = d_Lb[p];
    size_t mbase = (size_t)(t >> 8) * CLEN;
    const float2* bu = (const float2*)d_Bu + mbase * PD + p;
    float2 s = d_carry[t];
    #pragma unroll 4
    for (int l = 0; l < CLEN; l++) {
        float2 v = bu[(size_t)l * PD];
        float sr = fmaf(a.x, s.x, fmaf(-a.y, s.y, v.x));
        float si = fmaf(a.x, s.y, fmaf(a.y, s.x, v.y));
        s.x = sr; s.y = si;
        __nv_bfloat16 hr, lr, hi, li;
        split1(sr, hr, lr);
        split1(si, hi, li);
        size_t off = (mbase + l) * ND + 2 * p;
        __nv_bfloat162 hv = __halves2bfloat162(hr, hi);
        __nv_bfloat162 lv = __halves2bfloat162(lr, li);
        *(uint32_t*)(d_xshi + off) = *(uint32_t*)&hv;
        *(uint32_t*)(d_xslo + off) = *(uint32_t*)&lv;
    }
}

// ---------------- launch -------------------------------------------------------
extern "C" void kernel_launch(void* const* d_in, const int* in_sizes, int n_in,
                              void* d_out, int out_size) {
    const float* x   = (const float*)d_in[0];
    const float* Lre = (const float*)d_in[1];
    const float* Lim = (const float*)d_in[2];
    const float* Bin = (const float*)d_in[3];
    const float* Cin = (const float*)d_in[4];
    const float* Dv  = (const float*)d_in[5];
    const float* ls  = (const float*)d_in[6];
    float* out = (float*)d_out;

    __nv_bfloat16 *pxhi, *pxlo, *pxshi, *pxslo, *pW1h, *pW1l, *pW2h, *pW2l;
    float* pBu;
    cudaGetSymbolAddress((void**)&pxhi,  d_xhi);
    cudaGetSymbolAddress((void**)&pxlo,  d_xlo);
    cudaGetSymbolAddress((void**)&pxshi, d_xshi);
    cudaGetSymbolAddress((void**)&pxslo, d_xslo);
    cudaGetSymbolAddress((void**)&pW1h,  d_W1t_hi);
    cudaGetSymbolAddress((void**)&pW1l,  d_W1t_lo);
    cudaGetSymbolAddress((void**)&pW2h,  d_W2t_hi);
    cudaGetSymbolAddress((void**)&pW2l,  d_W2t_lo);
    cudaGetSymbolAddress((void**)&pBu,   d_Bu);

    cudaFuncSetAttribute(gemm_hmma<false>, cudaFuncAttributeMaxDynamicSharedMemorySize, GSM_TOTAL);
    cudaFuncSetAttribute(gemm_hmma<true>,  cudaFuncAttributeMaxDynamicSharedMemorySize, GSM_TOTAL);

    k_prep1<<<1, 256>>>(Lre, Lim, ls);
    k_prep2<<<(PD * HD + 255) / 256, 256>>>(Bin, Cin);
    k_split<<<(int)(((size_t)MM * KD / 4) / 256), 256>>>(x);

    dim3 ggrid(ND / 128, MM / 128);   // (4, 256)
    gemm_hmma<false><<<ggrid, 256, GSM_TOTAL>>>(pxhi, pxlo, pW1h, pW1l, pBu, nullptr, nullptr);

    k_scan1<<<(BSZ * NCH * PD) / 256, 256>>>();
    k_scan2<<<(BSZ * PD) / 256, 256>>>();
    k_scan3<<<(BSZ * NCH * PD) / 256, 256>>>();

    gemm_hmma<true><<<ggrid, 256, GSM_TOTAL>>>(pxshi, pxslo, pW2h, pW2l, out, x, Dv);
}

// round 12
// speedup vs baseline: 1.0725x; 1.0354x over previous
#include <cuda_runtime.h>
#include <cuda_bf16.h>
#include <cstdint>
#include <cstddef>

// ---------------- problem constants ------------------------------------------
#define BSZ  8
#define LEN  4096
#define HD   512
#define PD   256
#define MM   (BSZ * LEN)   // 32768
#define KD   512           // GEMM K (both GEMMs)
#define ND   512           // GEMM N (both GEMMs)
#define NCH  128           // scan chunks per sequence
#define CLEN 32            // chunk length (NCH*CLEN == LEN)

// ---------------- device scratch ---------------------------------------------
__device__ __align__(128) __nv_bfloat16 d_xhi[(size_t)MM * KD];     // 32 MB
__device__ __align__(128) __nv_bfloat16 d_xlo[(size_t)MM * KD];     // 32 MB
__device__ __align__(128) __nv_bfloat16 d_xshi[(size_t)MM * KD];    // 32 MB
__device__ __align__(128) __nv_bfloat16 d_xslo[(size_t)MM * KD];    // 32 MB
__device__ __align__(128) float         d_Bu[(size_t)MM * ND];      // 64 MB
__device__ __align__(128) __nv_bfloat16 d_W1t_hi[ND * KD];          // [n=2p+j][k=h]
__device__ __align__(128) __nv_bfloat16 d_W1t_lo[ND * KD];
__device__ __align__(128) __nv_bfloat16 d_W2t_hi[ND * KD];          // [n=h][k=2p+j]
__device__ __align__(128) __nv_bfloat16 d_W2t_lo[ND * KD];
__device__ float2 d_Lb[PD];
__device__ float2 d_gamma[PD];
__device__ float2 d_Ach[PD];                                        // Lb^CLEN
__device__ float2 d_fin[BSZ * NCH * PD];
__device__ float2 d_carry[BSZ * NCH * PD];

// ---------------- helpers ------------------------------------------------------
__device__ __forceinline__ uint32_t smem_u32(const void* p) {
    uint32_t a;
    asm("{ .reg .u64 t; cvta.to.shared.u64 t, %1; cvt.u32.u64 %0, t; }" : "=r"(a) : "l"(p));
    return a;
}
__device__ __forceinline__ uint32_t swz128(uint32_t o) { return o ^ ((o >> 3) & 0x70); }

__device__ __forceinline__ void cp16(uint32_t s, const void* g) {
    asm volatile("cp.async.cg.shared.global [%0], [%1], 16;" :: "r"(s), "l"(g) : "memory");
}
#define CP_COMMIT() asm volatile("cp.async.commit_group;" ::: "memory")
#define CP_WAIT1()  asm volatile("cp.async.wait_group 1;" ::: "memory")
#define CP_WAIT0()  asm volatile("cp.async.wait_group 0;" ::: "memory")

__device__ __forceinline__ void ldsm4(uint32_t* r, uint32_t addr) {
    asm volatile("ldmatrix.sync.aligned.m8n8.x4.shared.b16 {%0,%1,%2,%3}, [%4];"
                 : "=r"(r[0]), "=r"(r[1]), "=r"(r[2]), "=r"(r[3]) : "r"(addr));
}
__device__ __forceinline__ void mma_bf16(float* d, const uint32_t* a, const uint32_t* b) {
    asm volatile(
        "mma.sync.aligned.m16n8k16.row.col.f32.bf16.bf16.f32 "
        "{%0,%1,%2,%3}, {%4,%5,%6,%7}, {%8,%9}, {%0,%1,%2,%3};"
        : "+f"(d[0]), "+f"(d[1]), "+f"(d[2]), "+f"(d[3])
        : "r"(a[0]), "r"(a[1]), "r"(a[2]), "r"(a[3]), "r"(b[0]), "r"(b[1]));
}
__device__ __forceinline__ void split1(float v, __nv_bfloat16& h, __nv_bfloat16& l) {
    h = __float2bfloat16_rn(v);
    l = __float2bfloat16_rn(v - __bfloat162float(h));
}

// ---------------- prep kernels ------------------------------------------------
__global__ void k_prep1(const float* __restrict__ Lre, const float* __restrict__ Lim,
                        const float* __restrict__ lstep) {
    int p = threadIdx.x;
    if (p < PD) {
        float step = expf(lstep[p]);
        float re = Lre[p], im = Lim[p];
        float er = expf(re * step);
        float sphi, cphi;
        sincosf(im * step, &sphi, &cphi);
        float2 Lb = make_float2(er * cphi, er * sphi);
        float nr = Lb.x - 1.0f, ni = Lb.y;
        float den = re * re + im * im;
        d_Lb[p] = Lb;
        d_gamma[p] = make_float2((nr * re + ni * im) / den, (ni * re - nr * im) / den);
        float2 a = Lb;
        #pragma unroll
        for (int i = 0; i < 5; i++) {   // Lb^32 (CLEN = 32 = 2^5)
            float ar = a.x * a.x - a.y * a.y;
            float ai = 2.0f * a.x * a.y;
            a = make_float2(ar, ai);
        }
        d_Ach[p] = a;
    }
}

__global__ void k_prep2(const float* __restrict__ Bin, const float* __restrict__ Cin) {
    int idx = blockIdx.x * blockDim.x + threadIdx.x;
    if (idx < PD * HD) {
        int p = idx / HD, h = idx % HD;
        float2 g = d_gamma[p];
        float br = Bin[(p * HD + h) * 2 + 0];
        float bi = Bin[(p * HD + h) * 2 + 1];
        float w1r = g.x * br - g.y * bi;   // n = 2p
        float w1i = g.x * bi + g.y * br;   // n = 2p+1
        __nv_bfloat16 hh, ll;
        split1(w1r, hh, ll); d_W1t_hi[(2 * p + 0) * KD + h] = hh; d_W1t_lo[(2 * p + 0) * KD + h] = ll;
        split1(w1i, hh, ll); d_W1t_hi[(2 * p + 1) * KD + h] = hh; d_W1t_lo[(2 * p + 1) * KD + h] = ll;
        float cr = Cin[(h * PD + p) * 2 + 0];
        float ci = Cin[(h * PD + p) * 2 + 1];
        split1( 2.0f * cr, hh, ll); d_W2t_hi[h * KD + 2 * p + 0] = hh; d_W2t_lo[h * KD + 2 * p + 0] = ll;
        split1(-2.0f * ci, hh, ll); d_W2t_hi[h * KD + 2 * p + 1] = hh; d_W2t_lo[h * KD + 2 * p + 1] = ll;
    }
}

__global__ void __launch_bounds__(256) k_split(const float* __restrict__ x) {
    size_t i = (size_t)blockIdx.x * 256 + threadIdx.x;
    float4 v = *(const float4*)(x + i * 4);
    __nv_bfloat16 h0, h1, h2, h3, l0, l1, l2, l3;
    split1(v.x, h0, l0); split1(v.y, h1, l1); split1(v.z, h2, l2); split1(v.w, h3, l3);
    __nv_bfloat162 hi01 = __halves2bfloat162(h0, h1), hi23 = __halves2bfloat162(h2, h3);
    __nv_bfloat162 lo01 = __halves2bfloat162(l0, l1), lo23 = __halves2bfloat162(l2, l3);
    ((uint2*)d_xhi)[i] = make_uint2(*(uint32_t*)&hi01, *(uint32_t*)&hi23);
    ((uint2*)d_xlo)[i] = make_uint2(*(uint32_t*)&lo01, *(uint32_t*)&lo23);
}

// ---------------- HMMA GEMM: 128x128 CTA, 8 warps (32x64 warp tile) -----------
// Superchunk: CHK=32 K-cols; stage row = [hi 64B | lo 64B] (128B, SW128).
// Per ks: front-load ahi+alo+bhi, burst alo*bhi (hides nothing, covered by
// prev burst / other warps), then ldsm blo + cp.async quarter, burst ahi*bhi
// (hides blo latency), burst ahi*blo. smem: 3 x 32KB = 96KB -> 2 CTAs/SM.
#define CHK    32
#define NC     16
#define STG_A(s)  ((s) * 16384u)
#define STG_B(s)  (49152u + (s) * 16384u)
#define GSM_TOTAL 98304

template <bool EPI>
__global__ void __launch_bounds__(256, 2)
gemm_hmma(const __nv_bfloat16* __restrict__ Ahi, const __nv_bfloat16* __restrict__ Alo,
          const __nv_bfloat16* __restrict__ Whi, const __nv_bfloat16* __restrict__ Wlo,
          float* __restrict__ Cout, const float* __restrict__ Xs, const float* __restrict__ Dv) {
    extern __shared__ char smem[];
    uint32_t sb = smem_u32(smem);
    const int tid = threadIdx.x, wid = tid >> 5, lane = tid & 31;
    const int wm = wid & 3, wn = wid >> 2;            // 4 x 2 warp grid
    const int m0 = blockIdx.y * 128, n0 = blockIdx.x * 128;

    // cp.async geometry: c16 = tid&7 fixed per thread; c16<4 -> hi half, else lo
    const int cprow0 = tid >> 3;               // 0..31 (+ i*32)
    const int cpc16  = tid & 7;
    const uint32_t cpcol = (uint32_t)cpc16 * 16;
    const __nv_bfloat16* Asrc = (cpc16 < 4) ? (Ahi + cpc16 * 8) : (Alo + (cpc16 - 4) * 8);
    const __nv_bfloat16* Wsrc = (cpc16 < 4) ? (Whi + cpc16 * 8) : (Wlo + (cpc16 - 4) * 8);

    // ldsm per-lane swizzled base offsets; XOR with ks*32 (bit5) / 64 (bit6)
    const uint32_t offA0 = swz128((wm * 32 + (lane & 15)) * 128 + (lane >> 4) * 16);
    const uint32_t offA1 = swz128((wm * 32 + 16 + (lane & 15)) * 128 + (lane >> 4) * 16);
    const int rowB = wn * 64 + ((lane >> 4) & 1) * 8 + (lane & 7);
    const uint32_t colB = ((lane >> 3) & 1) * 16;
    uint32_t offB[4];
    #pragma unroll
    for (int nt2 = 0; nt2 < 4; nt2++)
        offB[nt2] = swz128((rowB + nt2 * 16) * 128 + colB);

    float acc[2][8][4];
    #pragma unroll
    for (int i = 0; i < 2; i++)
        #pragma unroll
        for (int j = 0; j < 8; j++)
            #pragma unroll
            for (int q = 0; q < 4; q++) acc[i][j][q] = 0.0f;

    // prologue: issue chunks 0 and 1
    #pragma unroll
    for (int g = 0; g < 2; g++) {
        uint32_t ab = sb + STG_A(g), bb = sb + STG_B(g);
        int kc = g * CHK;
        #pragma unroll
        for (int i = 0; i < 4; i++) {
            int row = cprow0 + i * 32;
            uint32_t d = swz128(row * 128 + cpcol);
            cp16(ab + d, Asrc + (size_t)(m0 + row) * KD + kc);
            cp16(bb + d, Wsrc + (size_t)(n0 + row) * KD + kc);
        }
        CP_COMMIT();
    }

    for (int c = 0; c < NC; c++) {
        CP_WAIT1();
        __syncthreads();
        const bool pf = (c + 2 < NC);
        const int cn = c + 2;
        const uint32_t ab = sb + STG_A(cn % 3), bb = sb + STG_B(cn % 3);
        const int kc = cn * CHK;
        const uint32_t aB = sb + STG_A(c % 3), bB = sb + STG_B(c % 3);
        #pragma unroll
        for (int ks = 0; ks < 2; ks++) {
            const uint32_t kx = ks * 32;
            uint32_t ahi[2][4], alo[2][4], bhi[4][4], blo[4][4];
            // front batch: ahi, alo, bhi
            ldsm4(ahi[0], aB + (offA0 ^ kx));
            ldsm4(ahi[1], aB + (offA1 ^ kx));
            ldsm4(alo[0], aB + (offA0 ^ kx ^ 64u));
            ldsm4(alo[1], aB + (offA1 ^ kx ^ 64u));
            #pragma unroll
            for (int nt2 = 0; nt2 < 4; nt2++)
                ldsm4(bhi[nt2], bB + (offB[nt2] ^ kx));
            // burst 1: alo * bhi  (alo dies after this)
            #pragma unroll
            for (int mt = 0; mt < 2; mt++)
                #pragma unroll
                for (int nt = 0; nt < 8; nt++)
                    mma_bf16(acc[mt][nt], alo[mt], &bhi[nt >> 1][(nt & 1) * 2]);
            // ldsm blo + cp.async quarter; both hidden by burst 2
            #pragma unroll
            for (int nt2 = 0; nt2 < 4; nt2++)
                ldsm4(blo[nt2], bB + (offB[nt2] ^ kx ^ 64u));
            if (pf) {
                #pragma unroll
                for (int i = 0; i < 2; i++) {
                    int row = cprow0 + (ks * 2 + i) * 32;
                    uint32_t d = swz128(row * 128 + cpcol);
                    cp16(ab + d, Asrc + (size_t)(m0 + row) * KD + kc);
                    cp16(bb + d, Wsrc + (size_t)(n0 + row) * KD + kc);
                }
            }
            // burst 2: ahi * bhi (independent of blo -> hides its latency; bhi dies)
            #pragma unroll
            for (int mt = 0; mt < 2; mt++)
                #pragma unroll
                for (int nt = 0; nt < 8; nt++)
                    mma_bf16(acc[mt][nt], ahi[mt], &bhi[nt >> 1][(nt & 1) * 2]);
            // burst 3: ahi * blo
            #pragma unroll
            for (int mt = 0; mt < 2; mt++)
                #pragma unroll
                for (int nt = 0; nt < 8; nt++)
                    mma_bf16(acc[mt][nt], ahi[mt], &blo[nt >> 1][(nt & 1) * 2]);
        }
        CP_COMMIT();   // one group per iteration (possibly empty)
    }
    CP_WAIT0();

    // epilogue: d0,d1 -> (row g, col 2t..2t+1); d2,d3 -> row g+8
    const int g = lane >> 2, tig = lane & 3;
    #pragma unroll
    for (int mt = 0; mt < 2; mt++) {
        #pragma unroll
        for (int nt = 0; nt < 8; nt++) {
            int r0 = m0 + wm * 32 + mt * 16 + g;
            int cc = n0 + wn * 64 + nt * 8 + tig * 2;
            float2 v0 = make_float2(acc[mt][nt][0], acc[mt][nt][1]);
            float2 v1 = make_float2(acc[mt][nt][2], acc[mt][nt][3]);
            if (EPI) {
                float2 dv = *(const float2*)(Dv + cc);
                float2 x0 = *(const float2*)(Xs + (size_t)r0 * ND + cc);
                float2 x1 = *(const float2*)(Xs + (size_t)(r0 + 8) * ND + cc);
                v0.x = fmaf(dv.x, x0.x, v0.x); v0.y = fmaf(dv.y, x0.y, v0.y);
                v1.x = fmaf(dv.x, x1.x, v1.x); v1.y = fmaf(dv.y, x1.y, v1.y);
            }
            *(float2*)(Cout + (size_t)r0 * ND + cc) = v0;
            *(float2*)(Cout + (size_t)(r0 + 8) * ND + cc) = v1;
        }
    }
}

// ---------------- chunked complex scan ----------------------------------------
__global__ void __launch_bounds__(256) k_scan1() {
    int t = blockIdx.x * 256 + threadIdx.x;          // (b*NCH+ch)*PD + p
    int p = t & (PD - 1);
    float2 a = d_Lb[p];
    const float2* bu = (const float2*)d_Bu + (size_t)(t >> 8) * (CLEN * PD) + p;
    float2 s = make_float2(0.0f, 0.0f);
    #pragma unroll 4
    for (int l = 0; l < CLEN; l++) {
        float2 v = bu[(size_t)l * PD];
        float sr = fmaf(a.x, s.x, fmaf(-a.y, s.y, v.x));
        float si = fmaf(a.x, s.y, fmaf(a.y, s.x, v.y));
        s.x = sr; s.y = si;
    }
    d_fin[t] = s;
}

__global__ void __launch_bounds__(256) k_scan2() {
    int t = blockIdx.x * 256 + threadIdx.x;          // b*PD + p
    int p = t & (PD - 1);
    int b = t >> 8;
    float2 A = d_Ach[p];
    float2 c = make_float2(0.0f, 0.0f);
    for (int ch = 0; ch < NCH; ch++) {
        int idx = (b * NCH + ch) * PD + p;
        d_carry[idx] = c;
        float2 f = d_fin[idx];
        float cr = fmaf(A.x, c.x, fmaf(-A.y, c.y, f.x));
        float ci = fmaf(A.x, c.y, fmaf(A.y, c.x, f.y));
        c.x = cr; c.y = ci;
    }
}

__global__ void __launch_bounds__(256) k_scan3() {
    int t = blockIdx.x * 256 + threadIdx.x;
    int p = t & (PD - 1);
    float2 a = d_Lb[p];
    size_t mbase = (size_t)(t >> 8) * CLEN;
    const float2* bu = (const float2*)d_Bu + mbase * PD + p;
    float2 s = d_carry[t];
    #pragma unroll 4
    for (int l = 0; l < CLEN; l++) {
        float2 v = bu[(size_t)l * PD];
        float sr = fmaf(a.x, s.x, fmaf(-a.y, s.y, v.x));
        float si = fmaf(a.x, s.y, fmaf(a.y, s.x, v.y));
        s.x = sr; s.y = si;
        __nv_bfloat16 hr, lr, hi, li;
        split1(sr, hr, lr);
        split1(si, hi, li);
        size_t off = (mbase + l) * ND + 2 * p;
        __nv_bfloat162 hv = __halves2bfloat162(hr, hi);
        __nv_bfloat162 lv = __halves2bfloat162(lr, li);
        *(uint32_t*)(d_xshi + off) = *(uint32_t*)&hv;
        *(uint32_t*)(d_xslo + off) = *(uint32_t*)&lv;
    }
}

// ---------------- launch -------------------------------------------------------
extern "C" void kernel_launch(void* const* d_in, const int* in_sizes, int n_in,
                              void* d_out, int out_size) {
    const float* x   = (const float*)d_in[0];
    const float* Lre = (const float*)d_in[1];
    const float* Lim = (const float*)d_in[2];
    const float* Bin = (const float*)d_in[3];
    const float* Cin = (const float*)d_in[4];
    const float* Dv  = (const float*)d_in[5];
    const float* ls  = (const float*)d_in[6];
    float* out = (float*)d_out;

    __nv_bfloat16 *pxhi, *pxlo, *pxshi, *pxslo, *pW1h, *pW1l, *pW2h, *pW2l;
    float* pBu;
    cudaGetSymbolAddress((void**)&pxhi,  d_xhi);
    cudaGetSymbolAddress((void**)&pxlo,  d_xlo);
    cudaGetSymbolAddress((void**)&pxshi, d_xshi);
    cudaGetSymbolAddress((void**)&pxslo, d_xslo);
    cudaGetSymbolAddress((void**)&pW1h,  d_W1t_hi);
    cudaGetSymbolAddress((void**)&pW1l,  d_W1t_lo);
    cudaGetSymbolAddress((void**)&pW2h,  d_W2t_hi);
    cudaGetSymbolAddress((void**)&pW2l,  d_W2t_lo);
    cudaGetSymbolAddress((void**)&pBu,   d_Bu);

    cudaFuncSetAttribute(gemm_hmma<false>, cudaFuncAttributeMaxDynamicSharedMemorySize, GSM_TOTAL);
    cudaFuncSetAttribute(gemm_hmma<true>,  cudaFuncAttributeMaxDynamicSharedMemorySize, GSM_TOTAL);

    k_prep1<<<1, 256>>>(Lre, Lim, ls);
    k_prep2<<<(PD * HD + 255) / 256, 256>>>(Bin, Cin);
    k_split<<<(int)(((size_t)MM * KD / 4) / 256), 256>>>(x);

    dim3 ggrid(ND / 128, MM / 128);   // (4, 256)
    gemm_hmma<false><<<ggrid, 256, GSM_TOTAL>>>(pxhi, pxlo, pW1h, pW1l, pBu, nullptr, nullptr);

    k_scan1<<<(BSZ * NCH * PD) / 256, 256>>>();
    k_scan2<<<(BSZ * PD) / 256, 256>>>();
    k_scan3<<<(BSZ * NCH * PD) / 256, 256>>>();

    gemm_hmma<true><<<ggrid, 256, GSM_TOTAL>>>(pxshi, pxslo, pW2h, pW2l, out, x, Dv);
}

// round 14
// speedup vs baseline: 1.3876x; 1.2938x over previous
#include <cuda_runtime.h>
#include <cuda_bf16.h>
#include <cuda_fp16.h>
#include <cstdint>
#include <cstddef>

// ---------------- problem constants ------------------------------------------
#define BSZ  8
#define LEN  4096
#define HD   512
#define PD   256
#define MM   (BSZ * LEN)   // 32768
#define KD   512           // GEMM K (both GEMMs)
#define ND   512           // GEMM N (both GEMMs)
#define NCH  128           // scan chunks per sequence
#define CLEN 32            // chunk length (NCH*CLEN == LEN)

// ---------------- device scratch ---------------------------------------------
__device__ __align__(128) __half d_xh [(size_t)MM * KD];     // 32 MB (x fp16)
__device__ __align__(128) __half d_xsh[(size_t)MM * KD];     // 32 MB (xs fp16, unscaled)
__device__ __align__(128) float  d_Bu [(size_t)MM * ND];     // 64 MB (Bu, p-row-scaled)
__device__ __align__(128) __half d_W1t_hi[ND * KD];          // [n=2p+j][k=h], scaled by s_p
__device__ __align__(128) __half d_W1t_lo[ND * KD];
__device__ __align__(128) __half d_W2t_hi[ND * KD];          // [n=h][k=2p+j]
__device__ __align__(128) __half d_W2t_lo[ND * KD];
__device__ float2 d_Lb[PD];
__device__ float2 d_gamma[PD];
__device__ float2 d_Ach[PD];                                 // Lb^CLEN
__device__ float  d_sS[PD];                                  // 2^e scale for W1 row p
__device__ float  d_invS[PD];                                // 2^-e
__device__ float2 d_fin[BSZ * NCH * PD];
__device__ float2 d_carry[BSZ * NCH * PD];

// ---------------- helpers ------------------------------------------------------
__device__ __forceinline__ uint32_t smem_u32(const void* p) {
    uint32_t a;
    asm("{ .reg .u64 t; cvta.to.shared.u64 t, %1; cvt.u32.u64 %0, t; }" : "=r"(a) : "l"(p));
    return a;
}
__device__ __forceinline__ uint32_t swz128(uint32_t o) { return o ^ ((o >> 3) & 0x70); }
__device__ __forceinline__ uint32_t swz64(uint32_t o)  { return o ^ ((o >> 3) & 0x30); }

__device__ __forceinline__ void cp16(uint32_t s, const void* g) {
    asm volatile("cp.async.cg.shared.global [%0], [%1], 16;" :: "r"(s), "l"(g) : "memory");
}
#define CP_COMMIT() asm volatile("cp.async.commit_group;" ::: "memory")
#define CP_WAIT1()  asm volatile("cp.async.wait_group 1;" ::: "memory")
#define CP_WAIT0()  asm volatile("cp.async.wait_group 0;" ::: "memory")

__device__ __forceinline__ void ldsm4(uint32_t* r, uint32_t addr) {
    asm volatile("ldmatrix.sync.aligned.m8n8.x4.shared.b16 {%0,%1,%2,%3}, [%4];"
                 : "=r"(r[0]), "=r"(r[1]), "=r"(r[2]), "=r"(r[3]) : "r"(addr));
}
__device__ __forceinline__ void mma_f16(float* d, const uint32_t* a, const uint32_t* b) {
    asm volatile(
        "mma.sync.aligned.m16n8k16.row.col.f32.f16.f16.f32 "
        "{%0,%1,%2,%3}, {%4,%5,%6,%7}, {%8,%9}, {%0,%1,%2,%3};"
        : "+f"(d[0]), "+f"(d[1]), "+f"(d[2]), "+f"(d[3])
        : "r"(a[0]), "r"(a[1]), "r"(a[2]), "r"(a[3]), "r"(b[0]), "r"(b[1]));
}
__device__ __forceinline__ void splitH(float v, __half& h, __half& l) {
    h = __float2half_rn(v);
    l = __float2half_rn(v - __half2float(h));
}

// ---------------- prep kernels ------------------------------------------------
__global__ void k_prep1(const float* __restrict__ Lre, const float* __restrict__ Lim,
                        const float* __restrict__ lstep) {
    int p = threadIdx.x;
    if (p < PD) {
        float step = expf(lstep[p]);
        float re = Lre[p], im = Lim[p];
        float er = expf(re * step);
        float sphi, cphi;
        sincosf(im * step, &sphi, &cphi);
        float2 Lb = make_float2(er * cphi, er * sphi);
        float nr = Lb.x - 1.0f, ni = Lb.y;
        float den = re * re + im * im;
        float2 g = make_float2((nr * re + ni * im) / den, (ni * re - nr * im) / den);
        d_Lb[p] = Lb;
        d_gamma[p] = g;
        // per-row power-of-2 scale so gamma*s ~ 1 (keeps W1 rows in fp16 sweet range)
        float gm = sqrtf(g.x * g.x + g.y * g.y);
        float e = rintf(log2f(gm));
        d_sS[p]   = exp2f(-e);
        d_invS[p] = exp2f(e);
        float2 a = Lb;
        #pragma unroll
        for (int i = 0; i < 5; i++) {   // Lb^32 (CLEN = 32 = 2^5)
            float ar = a.x * a.x - a.y * a.y;
            float ai = 2.0f * a.x * a.y;
            a = make_float2(ar, ai);
        }
        d_Ach[p] = a;
    }
}

__global__ void k_prep2(const float* __restrict__ Bin, const float* __restrict__ Cin) {
    int idx = blockIdx.x * blockDim.x + threadIdx.x;
    if (idx < PD * HD) {
        int p = idx / HD, h = idx % HD;
        float2 g = d_gamma[p];
        float s = d_sS[p];
        float br = Bin[(p * HD + h) * 2 + 0];
        float bi = Bin[(p * HD + h) * 2 + 1];
        float w1r = (g.x * br - g.y * bi) * s;   // n = 2p   (scaled)
        float w1i = (g.x * bi + g.y * br) * s;   // n = 2p+1
        __half hh, ll;
        splitH(w1r, hh, ll); d_W1t_hi[(2 * p + 0) * KD + h] = hh; d_W1t_lo[(2 * p + 0) * KD + h] = ll;
        splitH(w1i, hh, ll); d_W1t_hi[(2 * p + 1) * KD + h] = hh; d_W1t_lo[(2 * p + 1) * KD + h] = ll;
        float cr = Cin[(h * PD + p) * 2 + 0];
        float ci = Cin[(h * PD + p) * 2 + 1];
        splitH( 2.0f * cr, hh, ll); d_W2t_hi[h * KD + 2 * p + 0] = hh; d_W2t_lo[h * KD + 2 * p + 0] = ll;
        splitH(-2.0f * ci, hh, ll); d_W2t_hi[h * KD + 2 * p + 1] = hh; d_W2t_lo[h * KD + 2 * p + 1] = ll;
    }
}

__global__ void __launch_bounds__(256) k_split(const float* __restrict__ x) {
    size_t i = (size_t)blockIdx.x * 256 + threadIdx.x;
    float4 v = *(const float4*)(x + i * 4);
    __half2 a = __floats2half2_rn(v.x, v.y);
    __half2 b = __floats2half2_rn(v.z, v.w);
    ((uint2*)d_xh)[i] = make_uint2(*(uint32_t*)&a, *(uint32_t*)&b);
}

// ---------------- HMMA GEMM: 128x128 CTA, 8 warps (32x64 warp tile) -----------
// fp16 2-product: A single fp16 (SW64 rows, 64B), W rows = [hi 64B | lo 64B]
// (SW128). Per ks: ldsm ahi+bhi, burst ahi*bhi; ldsm blo (+cp.async), burst
// ahi*blo. smem: 3 stages x (A 8KB + B 16KB) = 72KB -> 2 CTAs/SM.
#define CHK    32
#define NC     16
#define STG_A(s)  ((s) * 8192u)
#define STG_B(s)  (24576u + (s) * 16384u)
#define GSM_TOTAL 73728

template <bool EPI>
__global__ void __launch_bounds__(256, 2)
gemm_hmma(const __half* __restrict__ Ah,
          const __half* __restrict__ Whi, const __half* __restrict__ Wlo,
          float* __restrict__ Cout, const float* __restrict__ Xs, const float* __restrict__ Dv) {
    extern __shared__ char smem[];
    uint32_t sb = smem_u32(smem);
    const int tid = threadIdx.x, wid = tid >> 5, lane = tid & 31;
    const int wm = wid & 3, wn = wid >> 2;            // 4 x 2 warp grid
    const int m0 = blockIdx.y * 128, n0 = blockIdx.x * 128;

    // cp.async geometry
    const int arow0 = tid >> 2;                 // 0..63 (+ i*64), A: 128r x 64B
    const int ac16  = tid & 3;
    const uint32_t acol = (uint32_t)ac16 * 16;
    const int brow0 = tid >> 3;                 // 0..31 (+ i*32), B: 128r x 128B
    const int bc16  = tid & 7;
    const uint32_t bcol = (uint32_t)bc16 * 16;
    const __half* Wsrc = (bc16 < 4) ? (Whi + bc16 * 8) : (Wlo + (bc16 - 4) * 8);

    // ldsm per-lane swizzled base offsets
    uint32_t offA[2];
    #pragma unroll
    for (int mt = 0; mt < 2; mt++)
        offA[mt] = swz64((wm * 32 + mt * 16 + (lane & 15)) * 64 + (lane >> 4) * 16);
    const int rowB = wn * 64 + ((lane >> 4) & 1) * 8 + (lane & 7);
    const uint32_t colB = ((lane >> 3) & 1) * 16;
    uint32_t offB[4];
    #pragma unroll
    for (int nt2 = 0; nt2 < 4; nt2++)
        offB[nt2] = swz128((rowB + nt2 * 16) * 128 + colB);

    float acc[2][8][4];
    #pragma unroll
    for (int i = 0; i < 2; i++)
        #pragma unroll
        for (int j = 0; j < 8; j++)
            #pragma unroll
            for (int q = 0; q < 4; q++) acc[i][j][q] = 0.0f;

    // prologue: issue chunks 0 and 1
    #pragma unroll
    for (int g = 0; g < 2; g++) {
        uint32_t ab = sb + STG_A(g), bb = sb + STG_B(g);
        int kc = g * CHK;
        #pragma unroll
        for (int i = 0; i < 2; i++) {
            int row = arow0 + i * 64;
            cp16(ab + swz64(row * 64 + acol), Ah + (size_t)(m0 + row) * KD + kc + ac16 * 8);
        }
        #pragma unroll
        for (int i = 0; i < 4; i++) {
            int row = brow0 + i * 32;
            cp16(bb + swz128(row * 128 + bcol), Wsrc + (size_t)(n0 + row) * KD + kc);
        }
        CP_COMMIT();
    }

    for (int c = 0; c < NC; c++) {
        CP_WAIT1();
        __syncthreads();
        const bool pf = (c + 2 < NC);
        const int cn = c + 2;
        const uint32_t ab = sb + STG_A(cn % 3), bb = sb + STG_B(cn % 3);
        const int kc = cn * CHK;
        const uint32_t aB = sb + STG_A(c % 3), bB = sb + STG_B(c % 3);
        #pragma unroll
        for (int ks = 0; ks < 2; ks++) {
            const uint32_t kx = ks * 32;
            uint32_t ahi[2][4], bhi[4][4], blo[4][4];
            ldsm4(ahi[0], aB + (offA[0] ^ kx));
            ldsm4(ahi[1], aB + (offA[1] ^ kx));
            #pragma unroll
            for (int nt2 = 0; nt2 < 4; nt2++)
                ldsm4(bhi[nt2], bB + (offB[nt2] ^ kx));
            // burst 1: ahi * bhi
            #pragma unroll
            for (int mt = 0; mt < 2; mt++)
                #pragma unroll
                for (int nt = 0; nt < 8; nt++)
                    mma_f16(acc[mt][nt], ahi[mt], &bhi[nt >> 1][(nt & 1) * 2]);
            // ldsm blo + cp.async portion; hidden by burst 1 issue / burst 2
            #pragma unroll
            for (int nt2 = 0; nt2 < 4; nt2++)
                ldsm4(blo[nt2], bB + (offB[nt2] ^ kx ^ 64u));
            if (pf) {
                if (ks == 0) {
                    #pragma unroll
                    for (int i = 0; i < 2; i++) {
                        int row = arow0 + i * 64;
                        cp16(ab + swz64(row * 64 + acol),
                             Ah + (size_t)(m0 + row) * KD + kc + ac16 * 8);
                    }
                    #pragma unroll
                    for (int i = 0; i < 2; i++) {
                        int row = brow0 + i * 32;
                        cp16(bb + swz128(row * 128 + bcol),
                             Wsrc + (size_t)(n0 + row) * KD + kc);
                    }
                } else {
                    #pragma unroll
                    for (int i = 2; i < 4; i++) {
                        int row = brow0 + i * 32;
                        cp16(bb + swz128(row * 128 + bcol),
                             Wsrc + (size_t)(n0 + row) * KD + kc);
                    }
                }
            }
            // burst 2: ahi * blo
            #pragma unroll
            for (int mt = 0; mt < 2; mt++)
                #pragma unroll
                for (int nt = 0; nt < 8; nt++)
                    mma_f16(acc[mt][nt], ahi[mt], &blo[nt >> 1][(nt & 1) * 2]);
        }
        CP_COMMIT();   // one group per iteration (possibly empty)
    }
    CP_WAIT0();

    // epilogue: d0,d1 -> (row g, col 2t..2t+1); d2,d3 -> row g+8
    const int g = lane >> 2, tig = lane & 3;
    #pragma unroll
    for (int mt = 0; mt < 2; mt++) {
        #pragma unroll
        for (int nt = 0; nt < 8; nt++) {
            int r0 = m0 + wm * 32 + mt * 16 + g;
            int cc = n0 + wn * 64 + nt * 8 + tig * 2;
            float2 v0 = make_float2(acc[mt][nt][0], acc[mt][nt][1]);
            float2 v1 = make_float2(acc[mt][nt][2], acc[mt][nt][3]);
            if (EPI) {
                float2 dv = *(const float2*)(Dv + cc);
                float2 x0 = *(const float2*)(Xs + (size_t)r0 * ND + cc);
                float2 x1 = *(const float2*)(Xs + (size_t)(r0 + 8) * ND + cc);
                v0.x = fmaf(dv.x, x0.x, v0.x); v0.y = fmaf(dv.y, x0.y, v0.y);
                v1.x = fmaf(dv.x, x1.x, v1.x); v1.y = fmaf(dv.y, x1.y, v1.y);
            }
            *(float2*)(Cout + (size_t)r0 * ND + cc) = v0;
            *(float2*)(Cout + (size_t)(r0 + 8) * ND + cc) = v1;
        }
    }
}

// ---------------- chunked complex scan (on scaled Bu) --------------------------
__global__ void __launch_bounds__(256) k_scan1() {
    int t = blockIdx.x * 256 + threadIdx.x;          // (b*NCH+ch)*PD + p
    int p = t & (PD - 1);
    float2 a = d_Lb[p];
    const float2* bu = (const float2*)d_Bu + (size_t)(t >> 8) * (CLEN * PD) + p;
    float2 s = make_float2(0.0f, 0.0f);
    #pragma unroll 4
    for (int l = 0; l < CLEN; l++) {
        float2 v = bu[(size_t)l * PD];
        float sr = fmaf(a.x, s.x, fmaf(-a.y, s.y, v.x));
        float si = fmaf(a.x, s.y, fmaf(a.y, s.x, v.y));
        s.x = sr; s.y = si;
    }
    d_fin[t] = s;
}

__global__ void __launch_bounds__(256) k_scan2() {
    int t = blockIdx.x * 256 + threadIdx.x;          // b*PD + p
    int p = t & (PD - 1);
    int b = t >> 8;
    float2 A = d_Ach[p];
    float2 c = make_float2(0.0f, 0.0f);
    for (int ch = 0; ch < NCH; ch++) {
        int idx = (b * NCH + ch) * PD + p;
        d_carry[idx] = c;
        float2 f = d_fin[idx];
        float cr = fmaf(A.x, c.x, fmaf(-A.y, c.y, f.x));
        float ci = fmaf(A.x, c.y, fmaf(A.y, c.x, f.y));
        c.x = cr; c.y = ci;
    }
}

__global__ void __launch_bounds__(256) k_scan3() {
    int t = blockIdx.x * 256 + threadIdx.x;
    int p = t & (PD - 1);
    float2 a = d_Lb[p];
    float inv = d_invS[p];          // undo W1 row scaling (exact power of 2)
    size_t mbase = (size_t)(t >> 8) * CLEN;
    const float2* bu = (const float2*)d_Bu + mbase * PD + p;
    float2 s = d_carry[t];
    #pragma unroll 4
    for (int l = 0; l < CLEN; l++) {
        float2 v = bu[(size_t)l * PD];
        float sr = fmaf(a.x, s.x, fmaf(-a.y, s.y, v.x));
        float si = fmaf(a.x, s.y, fmaf(a.y, s.x, v.y));
        s.x = sr; s.y = si;
        size_t off = (mbase + l) * ND + 2 * p;
        __half2 hv = __floats2half2_rn(sr * inv, si * inv);
        *(uint32_t*)(d_xsh + off) = *(uint32_t*)&hv;
    }
}

// ---------------- launch -------------------------------------------------------
extern "C" void kernel_launch(void* const* d_in, const int* in_sizes, int n_in,
                              void* d_out, int out_size) {
    const float* x   = (const float*)d_in[0];
    const float* Lre = (const float*)d_in[1];
    const float* Lim = (const float*)d_in[2];
    const float* Bin = (const float*)d_in[3];
    const float* Cin = (const float*)d_in[4];
    const float* Dv  = (const float*)d_in[5];
    const float* ls  = (const float*)d_in[6];
    float* out = (float*)d_out;

    __half *pxh, *pxsh, *pW1h, *pW1l, *pW2h, *pW2l;
    float* pBu;
    cudaGetSymbolAddress((void**)&pxh,  d_xh);
    cudaGetSymbolAddress((void**)&pxsh, d_xsh);
    cudaGetSymbolAddress((void**)&pW1h, d_W1t_hi);
    cudaGetSymbolAddress((void**)&pW1l, d_W1t_lo);
    cudaGetSymbolAddress((void**)&pW2h, d_W2t_hi);
    cudaGetSymbolAddress((void**)&pW2l, d_W2t_lo);
    cudaGetSymbolAddress((void**)&pBu,  d_Bu);

    cudaFuncSetAttribute(gemm_hmma<false>, cudaFuncAttributeMaxDynamicSharedMemorySize, GSM_TOTAL);
    cudaFuncSetAttribute(gemm_hmma<true>,  cudaFuncAttributeMaxDynamicSharedMemorySize, GSM_TOTAL);

    k_prep1<<<1, 256>>>(Lre, Lim, ls);
    k_prep2<<<(PD * HD + 255) / 256, 256>>>(Bin, Cin);
    k_split<<<(int)(((size_t)MM * KD / 4) / 256), 256>>>(x);

    dim3 ggrid(ND / 128, MM / 128);   // (4, 256)
    gemm_hmma<false><<<ggrid, 256, GSM_TOTAL>>>(pxh, pW1h, pW1l, pBu, nullptr, nullptr);

    k_scan1<<<(BSZ * NCH * PD) / 256, 256>>>();
    k_scan2<<<(BSZ * PD) / 256, 256>>>();
    k_scan3<<<(BSZ * NCH * PD) / 256, 256>>>();

    gemm_hmma<true><<<ggrid, 256, GSM_TOTAL>>>(pxsh, pW2h, pW2l, out, x, Dv);
}

// round 16
// speedup vs baseline: 1.9406x; 1.3986x over previous
#include <cuda_runtime.h>
#include <cuda_bf16.h>
#include <cuda_fp16.h>
#include <cstdint>
#include <cstddef>

// ---------------- problem constants ------------------------------------------
#define BSZ  8
#define LEN  4096
#define HD   512
#define PD   256
#define MM   (BSZ * LEN)   // 32768
#define KD   512           // GEMM K (both GEMMs)
#define ND   512           // GEMM N (both GEMMs)
#define NCH  128           // scan chunks per sequence
#define CLEN 32            // chunk length (NCH*CLEN == LEN)

// ---------------- device scratch ---------------------------------------------
__device__ __align__(128) __half d_xh [(size_t)MM * KD];     // 32 MB (x fp16)
__device__ __align__(128) __half d_xsh[(size_t)MM * KD];     // 32 MB (xs fp16, unscaled)
__device__ __align__(128) float  d_Bu [(size_t)MM * ND];     // 64 MB (Bu, p-row-scaled)
__device__ __align__(128) __half d_W1t[ND * KD];             // [n=2p+j][k=h], scaled by s_p
__device__ __align__(128) __half d_W2t[ND * KD];             // [n=h][k=2p+j]
__device__ float2 d_Lb[PD];
__device__ float2 d_gamma[PD];
__device__ float2 d_Ach[PD];                                 // Lb^CLEN
__device__ float  d_sS[PD];                                  // 2^-e scale for W1 row p
__device__ float  d_invS[PD];                                // 2^e
__device__ float2 d_fin[BSZ * NCH * PD];
__device__ float2 d_carry[BSZ * NCH * PD];

// ---------------- helpers ------------------------------------------------------
__device__ __forceinline__ uint32_t smem_u32(const void* p) {
    uint32_t a;
    asm("{ .reg .u64 t; cvta.to.shared.u64 t, %1; cvt.u32.u64 %0, t; }" : "=r"(a) : "l"(p));
    return a;
}
__device__ __forceinline__ uint32_t swz128(uint32_t o) { return o ^ ((o >> 3) & 0x70); }

__device__ __forceinline__ void cp16(uint32_t s, const void* g) {
    asm volatile("cp.async.cg.shared.global [%0], [%1], 16;" :: "r"(s), "l"(g) : "memory");
}
#define CP_COMMIT() asm volatile("cp.async.commit_group;" ::: "memory")
#define CP_WAIT1()  asm volatile("cp.async.wait_group 1;" ::: "memory")
#define CP_WAIT0()  asm volatile("cp.async.wait_group 0;" ::: "memory")

__device__ __forceinline__ void ldsm4(uint32_t* r, uint32_t addr) {
    asm volatile("ldmatrix.sync.aligned.m8n8.x4.shared.b16 {%0,%1,%2,%3}, [%4];"
                 : "=r"(r[0]), "=r"(r[1]), "=r"(r[2]), "=r"(r[3]) : "r"(addr));
}
__device__ __forceinline__ void mma_f16(float* d, const uint32_t* a, const uint32_t* b) {
    asm volatile(
        "mma.sync.aligned.m16n8k16.row.col.f32.f16.f16.f32 "
        "{%0,%1,%2,%3}, {%4,%5,%6,%7}, {%8,%9}, {%0,%1,%2,%3};"
        : "+f"(d[0]), "+f"(d[1]), "+f"(d[2]), "+f"(d[3])
        : "r"(a[0]), "r"(a[1]), "r"(a[2]), "r"(a[3]), "r"(b[0]), "r"(b[1]));
}

// ---------------- prep kernels ------------------------------------------------
__global__ void k_prep1(const float* __restrict__ Lre, const float* __restrict__ Lim,
                        const float* __restrict__ lstep) {
    int p = threadIdx.x;
    if (p < PD) {
        float step = expf(lstep[p]);
        float re = Lre[p], im = Lim[p];
        float er = expf(re * step);
        float sphi, cphi;
        sincosf(im * step, &sphi, &cphi);
        float2 Lb = make_float2(er * cphi, er * sphi);
        float nr = Lb.x - 1.0f, ni = Lb.y;
        float den = re * re + im * im;
        float2 g = make_float2((nr * re + ni * im) / den, (ni * re - nr * im) / den);
        d_Lb[p] = Lb;
        d_gamma[p] = g;
        // per-row power-of-2 scale so gamma*s ~ 1 (keeps W1 rows in fp16 sweet range)
        float gm = sqrtf(g.x * g.x + g.y * g.y);
        float e = rintf(log2f(gm));
        d_sS[p]   = exp2f(-e);
        d_invS[p] = exp2f(e);
        float2 a = Lb;
        #pragma unroll
        for (int i = 0; i < 5; i++) {   // Lb^32 (CLEN = 32 = 2^5)
            float ar = a.x * a.x - a.y * a.y;
            float ai = 2.0f * a.x * a.y;
            a = make_float2(ar, ai);
        }
        d_Ach[p] = a;
    }
}

__global__ void k_prep2(const float* __restrict__ Bin, const float* __restrict__ Cin) {
    int idx = blockIdx.x * blockDim.x + threadIdx.x;
    if (idx < PD * HD) {
        int p = idx / HD, h = idx % HD;
        float2 g = d_gamma[p];
        float s = d_sS[p];
        float br = Bin[(p * HD + h) * 2 + 0];
        float bi = Bin[(p * HD + h) * 2 + 1];
        d_W1t[(2 * p + 0) * KD + h] = __float2half_rn((g.x * br - g.y * bi) * s);
        d_W1t[(2 * p + 1) * KD + h] = __float2half_rn((g.x * bi + g.y * br) * s);
        float cr = Cin[(h * PD + p) * 2 + 0];
        float ci = Cin[(h * PD + p) * 2 + 1];
        d_W2t[h * KD + 2 * p + 0] = __float2half_rn( 2.0f * cr);
        d_W2t[h * KD + 2 * p + 1] = __float2half_rn(-2.0f * ci);
    }
}

__global__ void __launch_bounds__(256) k_split(const float* __restrict__ x) {
    size_t i = (size_t)blockIdx.x * 256 + threadIdx.x;
    float4 v = *(const float4*)(x + i * 4);
    __half2 a = __floats2half2_rn(v.x, v.y);
    __half2 b = __floats2half2_rn(v.z, v.w);
    ((uint2*)d_xh)[i] = make_uint2(*(uint32_t*)&a, *(uint32_t*)&b);
}

// ---------------- HMMA GEMM: 128x128 CTA, 8 warps (32x64 warp tile) -----------
// Single fp16 product. CHK=64 (128B rows, SW128), 3 stages x 32KB = 96KB
// -> 2 CTAs/SM. Per ks: ldsm A(2)+B01 -> 8 MMA -> ldsm B23 + cp.async -> 8 MMA.
#define CHK    64
#define NC     8
#define STG_A(s)  ((s) * 16384u)
#define STG_B(s)  (49152u + (s) * 16384u)
#define GSM_TOTAL 98304

template <bool EPI>
__global__ void __launch_bounds__(256, 2)
gemm_hmma(const __half* __restrict__ Ah, const __half* __restrict__ W,
          float* __restrict__ Cout, const __half* __restrict__ Xsh,
          const float* __restrict__ Dv) {
    extern __shared__ char smem[];
    uint32_t sb = smem_u32(smem);
    const int tid = threadIdx.x, wid = tid >> 5, lane = tid & 31;
    const int wm = wid & 3, wn = wid >> 2;            // 4 x 2 warp grid
    const int m0 = blockIdx.y * 128, n0 = blockIdx.x * 128;

    // cp.async geometry: 128 rows x 8 c16 per tile; 4 per thread per tile
    const int cprow0 = tid >> 3;               // 0..31 (+ i*32)
    const int cpc16  = tid & 7;
    const uint32_t cpcol = (uint32_t)cpc16 * 16;
    const __half* Asrc = Ah + cpc16 * 8;
    const __half* Wsrc = W  + cpc16 * 8;

    // ldsm per-lane swizzled base offsets; XOR with kx (bits 5-6; disjoint)
    const uint32_t offA0 = swz128((wm * 32 + (lane & 15)) * 128 + (lane >> 4) * 16);
    const uint32_t offA1 = swz128((wm * 32 + 16 + (lane & 15)) * 128 + (lane >> 4) * 16);
    const int rowB = wn * 64 + ((lane >> 4) & 1) * 8 + (lane & 7);
    const uint32_t colB = ((lane >> 3) & 1) * 16;
    uint32_t offB[4];
    #pragma unroll
    for (int nt2 = 0; nt2 < 4; nt2++)
        offB[nt2] = swz128((rowB + nt2 * 16) * 128 + colB);

    float acc[2][8][4];
    #pragma unroll
    for (int i = 0; i < 2; i++)
        #pragma unroll
        for (int j = 0; j < 8; j++)
            #pragma unroll
            for (int q = 0; q < 4; q++) acc[i][j][q] = 0.0f;

    // prologue: issue chunks 0 and 1
    #pragma unroll
    for (int g = 0; g < 2; g++) {
        uint32_t ab = sb + STG_A(g), bb = sb + STG_B(g);
        int kc = g * CHK;
        #pragma unroll
        for (int i = 0; i < 4; i++) {
            int row = cprow0 + i * 32;
            uint32_t d = swz128(row * 128 + cpcol);
            cp16(ab + d, Asrc + (size_t)(m0 + row) * KD + kc);
            cp16(bb + d, Wsrc + (size_t)(n0 + row) * KD + kc);
        }
        CP_COMMIT();
    }

    for (int c = 0; c < NC; c++) {
        CP_WAIT1();
        __syncthreads();
        const bool pf = (c + 2 < NC);
        const int cn = c + 2;
        const uint32_t ab = sb + STG_A(cn % 3), bb = sb + STG_B(cn % 3);
        const int kc = cn * CHK;
        const uint32_t aB = sb + STG_A(c % 3), bB = sb + STG_B(c % 3);
        #pragma unroll
        for (int ks = 0; ks < 4; ks++) {
            const uint32_t kx = ks * 32;
            uint32_t afr[2][4], bfr[4][4];
            ldsm4(afr[0], aB + (offA0 ^ kx));
            ldsm4(afr[1], aB + (offA1 ^ kx));
            ldsm4(bfr[0], bB + (offB[0] ^ kx));
            ldsm4(bfr[1], bB + (offB[1] ^ kx));
            // burst 1: nt 0..3 (covers ldsm of B23 below)
            #pragma unroll
            for (int mt = 0; mt < 2; mt++)
                #pragma unroll
                for (int nt = 0; nt < 4; nt++)
                    mma_f16(acc[mt][nt], afr[mt], &bfr[nt >> 1][(nt & 1) * 2]);
            ldsm4(bfr[2], bB + (offB[2] ^ kx));
            ldsm4(bfr[3], bB + (offB[3] ^ kx));
            if (pf) {   // one A + one B cp16 per ks
                int row = cprow0 + ks * 32;
                uint32_t d = swz128(row * 128 + cpcol);
                cp16(ab + d, Asrc + (size_t)(m0 + row) * KD + kc);
                cp16(bb + d, Wsrc + (size_t)(n0 + row) * KD + kc);
            }
            // burst 2: nt 4..7
            #pragma unroll
            for (int mt = 0; mt < 2; mt++)
                #pragma unroll
                for (int nt = 4; nt < 8; nt++)
                    mma_f16(acc[mt][nt], afr[mt], &bfr[nt >> 1][(nt & 1) * 2]);
        }
        CP_COMMIT();   // one group per iteration (possibly empty)
    }
    CP_WAIT0();

    // epilogue: d0,d1 -> (row g, col 2t..2t+1); d2,d3 -> row g+8
    const int g = lane >> 2, tig = lane & 3;
    #pragma unroll
    for (int mt = 0; mt < 2; mt++) {
        #pragma unroll
        for (int nt = 0; nt < 8; nt++) {
            int r0 = m0 + wm * 32 + mt * 16 + g;
            int cc = n0 + wn * 64 + nt * 8 + tig * 2;
            float2 v0 = make_float2(acc[mt][nt][0], acc[mt][nt][1]);
            float2 v1 = make_float2(acc[mt][nt][2], acc[mt][nt][3]);
            if (EPI) {
                float2 dv = *(const float2*)(Dv + cc);
                __half2 xh0 = *(const __half2*)(Xsh + (size_t)r0 * ND + cc);
                __half2 xh1 = *(const __half2*)(Xsh + (size_t)(r0 + 8) * ND + cc);
                float2 x0 = __half22float2(xh0);
                float2 x1 = __half22float2(xh1);
                v0.x = fmaf(dv.x, x0.x, v0.x); v0.y = fmaf(dv.y, x0.y, v0.y);
                v1.x = fmaf(dv.x, x1.x, v1.x); v1.y = fmaf(dv.y, x1.y, v1.y);
            }
            *(float2*)(Cout + (size_t)r0 * ND + cc) = v0;
            *(float2*)(Cout + (size_t)(r0 + 8) * ND + cc) = v1;
        }
    }
}

// ---------------- chunked complex scan (on scaled Bu) --------------------------
__global__ void __launch_bounds__(256) k_scan1() {
    int t = blockIdx.x * 256 + threadIdx.x;          // (b*NCH+ch)*PD + p
    int p = t & (PD - 1);
    float2 a = d_Lb[p];
    const float2* bu = (const float2*)d_Bu + (size_t)(t >> 8) * (CLEN * PD) + p;
    float2 s = make_float2(0.0f, 0.0f);
    #pragma unroll 4
    for (int l = 0; l < CLEN; l++) {
        float2 v = bu[(size_t)l * PD];
        float sr = fmaf(a.x, s.x, fmaf(-a.y, s.y, v.x));
        float si = fmaf(a.x, s.y, fmaf(a.y, s.x, v.y));
        s.x = sr; s.y = si;
    }
    d_fin[t] = s;
}

__global__ void __launch_bounds__(256) k_scan2() {
    int t = blockIdx.x * 256 + threadIdx.x;          // b*PD + p
    int p = t & (PD - 1);
    int b = t >> 8;
    float2 A = d_Ach[p];
    float2 c = make_float2(0.0f, 0.0f);
    for (int ch = 0; ch < NCH; ch++) {
        int idx = (b * NCH + ch) * PD + p;
        d_carry[idx] = c;
        float2 f = d_fin[idx];
        float cr = fmaf(A.x, c.x, fmaf(-A.y, c.y, f.x));
        float ci = fmaf(A.x, c.y, fmaf(A.y, c.x, f.y));
        c.x = cr; c.y = ci;
    }
}

__global__ void __launch_bounds__(256) k_scan3() {
    int t = blockIdx.x * 256 + threadIdx.x;
    int p = t & (PD - 1);
    float2 a = d_Lb[p];
    float inv = d_invS[p];          // undo W1 row scaling (exact power of 2)
    size_t mbase = (size_t)(t >> 8) * CLEN;
    const float2* bu = (const float2*)d_Bu + mbase * PD + p;
    float2 s = d_carry[t];
    #pragma unroll 4
    for (int l = 0; l < CLEN; l++) {
        float2 v = bu[(size_t)l * PD];
        float sr = fmaf(a.x, s.x, fmaf(-a.y, s.y, v.x));
        float si = fmaf(a.x, s.y, fmaf(a.y, s.x, v.y));
        s.x = sr; s.y = si;
        size_t off = (mbase + l) * ND + 2 * p;
        __half2 hv = __floats2half2_rn(sr * inv, si * inv);
        *(uint32_t*)(d_xsh + off) = *(uint32_t*)&hv;
    }
}

// ---------------- launch -------------------------------------------------------
extern "C" void kernel_launch(void* const* d_in, const int* in_sizes, int n_in,
                              void* d_out, int out_size) {
    const float* x   = (const float*)d_in[0];
    const float* Lre = (const float*)d_in[1];
    const float* Lim = (const float*)d_in[2];
    const float* Bin = (const float*)d_in[3];
    const float* Cin = (const float*)d_in[4];
    const float* Dv  = (const float*)d_in[5];
    const float* ls  = (const float*)d_in[6];
    float* out = (float*)d_out;

    __half *pxh, *pxsh, *pW1, *pW2;
    float* pBu;
    cudaGetSymbolAddress((void**)&pxh,  d_xh);
    cudaGetSymbolAddress((void**)&pxsh, d_xsh);
    cudaGetSymbolAddress((void**)&pW1,  d_W1t);
    cudaGetSymbolAddress((void**)&pW2,  d_W2t);
    cudaGetSymbolAddress((void**)&pBu,  d_Bu);

    cudaFuncSetAttribute(gemm_hmma<false>, cudaFuncAttributeMaxDynamicSharedMemorySize, GSM_TOTAL);
    cudaFuncSetAttribute(gemm_hmma<true>,  cudaFuncAttributeMaxDynamicSharedMemorySize, GSM_TOTAL);

    k_prep1<<<1, 256>>>(Lre, Lim, ls);
    k_prep2<<<(PD * HD + 255) / 256, 256>>>(Bin, Cin);
    k_split<<<(int)(((size_t)MM * KD / 4) / 256), 256>>>(x);

    dim3 ggrid(ND / 128, MM / 128);   // (4, 256)
    gemm_hmma<false><<<ggrid, 256, GSM_TOTAL>>>(pxh, pW1, pBu, nullptr, nullptr);

    k_scan1<<<(BSZ * NCH * PD) / 256, 256>>>();
    k_scan2<<<(BSZ * PD) / 256, 256>>>();
    k_scan3<<<(BSZ * NCH * PD) / 256, 256>>>();

    gemm_hmma<true><<<ggrid, 256, GSM_TOTAL>>>(pxsh, pW2, out, pxh, Dv);
}

// round 17
// speedup vs baseline: 2.0524x; 1.0576x over previous
#include <cuda_runtime.h>
#include <cuda_bf16.h>
#include <cuda_fp16.h>
#include <cstdint>
#include <cstddef>

// ---------------- problem constants ------------------------------------------
#define BSZ  8
#define LEN  4096
#define HD   512
#define PD   256
#define MM   (BSZ * LEN)   // 32768
#define KD   512           // GEMM K (both GEMMs)
#define ND   512           // GEMM N (both GEMMs)
#define NCH  128           // scan chunks per sequence
#define CLEN 32            // chunk length (NCH*CLEN == LEN)

// ---------------- device scratch ---------------------------------------------
__device__ __align__(128) __half d_xh [(size_t)MM * KD];     // 32 MB (x fp16)
__device__ __align__(128) __half d_xsh[(size_t)MM * KD];     // 32 MB (xs fp16, unscaled)
__device__ __align__(128) __half d_Buh[(size_t)MM * ND];     // 32 MB (Bu fp16, p-row-scaled)
__device__ __align__(128) __half d_W1t[ND * KD];             // [n=2p+j][k=h], scaled by s_p
__device__ __align__(128) __half d_W2t[ND * KD];             // [n=h][k=2p+j]
__device__ float2 d_Lb[PD];
__device__ float2 d_gamma[PD];
__device__ float2 d_Ach[PD];                                 // Lb^CLEN
__device__ float  d_sS[PD];                                  // 2^-e scale for W1 row p
__device__ float  d_invS[PD];                                // 2^e
__device__ float2 d_fin[BSZ * NCH * PD];
__device__ float2 d_carry[BSZ * NCH * PD];

// ---------------- helpers ------------------------------------------------------
__device__ __forceinline__ uint32_t smem_u32(const void* p) {
    uint32_t a;
    asm("{ .reg .u64 t; cvta.to.shared.u64 t, %1; cvt.u32.u64 %0, t; }" : "=r"(a) : "l"(p));
    return a;
}
__device__ __forceinline__ uint32_t swz128(uint32_t o) { return o ^ ((o >> 3) & 0x70); }

__device__ __forceinline__ void cp16(uint32_t s, const void* g) {
    asm volatile("cp.async.cg.shared.global [%0], [%1], 16;" :: "r"(s), "l"(g) : "memory");
}
#define CP_COMMIT() asm volatile("cp.async.commit_group;" ::: "memory")
#define CP_WAIT1()  asm volatile("cp.async.wait_group 1;" ::: "memory")
#define CP_WAIT0()  asm volatile("cp.async.wait_group 0;" ::: "memory")

__device__ __forceinline__ void ldsm4(uint32_t* r, uint32_t addr) {
    asm volatile("ldmatrix.sync.aligned.m8n8.x4.shared.b16 {%0,%1,%2,%3}, [%4];"
                 : "=r"(r[0]), "=r"(r[1]), "=r"(r[2]), "=r"(r[3]) : "r"(addr));
}
__device__ __forceinline__ void mma_f16(float* d, const uint32_t* a, const uint32_t* b) {
    asm volatile(
        "mma.sync.aligned.m16n8k16.row.col.f32.f16.f16.f32 "
        "{%0,%1,%2,%3}, {%4,%5,%6,%7}, {%8,%9}, {%0,%1,%2,%3};"
        : "+f"(d[0]), "+f"(d[1]), "+f"(d[2]), "+f"(d[3])
        : "r"(a[0]), "r"(a[1]), "r"(a[2]), "r"(a[3]), "r"(b[0]), "r"(b[1]));
}

// ---------------- prep kernels ------------------------------------------------
__global__ void k_prep1(const float* __restrict__ Lre, const float* __restrict__ Lim,
                        const float* __restrict__ lstep) {
    int p = threadIdx.x;
    if (p < PD) {
        float step = expf(lstep[p]);
        float re = Lre[p], im = Lim[p];
        float er = expf(re * step);
        float sphi, cphi;
        sincosf(im * step, &sphi, &cphi);
        float2 Lb = make_float2(er * cphi, er * sphi);
        float nr = Lb.x - 1.0f, ni = Lb.y;
        float den = re * re + im * im;
        float2 g = make_float2((nr * re + ni * im) / den, (ni * re - nr * im) / den);
        d_Lb[p] = Lb;
        d_gamma[p] = g;
        // per-row power-of-2 scale so gamma*s ~ 1 (keeps W1 rows in fp16 sweet range)
        float gm = sqrtf(g.x * g.x + g.y * g.y);
        float e = rintf(log2f(gm));
        d_sS[p]   = exp2f(-e);
        d_invS[p] = exp2f(e);
        float2 a = Lb;
        #pragma unroll
        for (int i = 0; i < 5; i++) {   // Lb^32 (CLEN = 32 = 2^5)
            float ar = a.x * a.x - a.y * a.y;
            float ai = 2.0f * a.x * a.y;
            a = make_float2(ar, ai);
        }
        d_Ach[p] = a;
    }
}

__global__ void k_prep2(const float* __restrict__ Bin, const float* __restrict__ Cin) {
    int idx = blockIdx.x * blockDim.x + threadIdx.x;
    if (idx < PD * HD) {
        int p = idx / HD, h = idx % HD;
        float2 g = d_gamma[p];
        float s = d_sS[p];
        float br = Bin[(p * HD + h) * 2 + 0];
        float bi = Bin[(p * HD + h) * 2 + 1];
        d_W1t[(2 * p + 0) * KD + h] = __float2half_rn((g.x * br - g.y * bi) * s);
        d_W1t[(2 * p + 1) * KD + h] = __float2half_rn((g.x * bi + g.y * br) * s);
        float cr = Cin[(h * PD + p) * 2 + 0];
        float ci = Cin[(h * PD + p) * 2 + 1];
        d_W2t[h * KD + 2 * p + 0] = __float2half_rn( 2.0f * cr);
        d_W2t[h * KD + 2 * p + 1] = __float2half_rn(-2.0f * ci);
    }
}

__global__ void __launch_bounds__(256) k_split(const float* __restrict__ x) {
    size_t i = (size_t)blockIdx.x * 256 + threadIdx.x;
    float4 v = *(const float4*)(x + i * 4);
    __half2 a = __floats2half2_rn(v.x, v.y);
    __half2 b = __floats2half2_rn(v.z, v.w);
    ((uint2*)d_xh)[i] = make_uint2(*(uint32_t*)&a, *(uint32_t*)&b);
}

// ---------------- HMMA GEMM: 128x128 CTA, 8 warps (32x64 warp tile) -----------
// Single fp16 product. CHK=64 (128B rows, SW128), 3 stages x 32KB = 96KB
// -> 2 CTAs/SM. Per ks: ldsm A(2)+B01 -> 8 MMA -> ldsm B23 + cp.async -> 8 MMA.
// MODE 0: pack acc to __half2 -> Cout (GEMM1 -> Bu fp16).
// MODE 1: fp32 out + D*x skip (x fp16).
#define CHK    64
#define NC     8
#define STG_A(s)  ((s) * 16384u)
#define STG_B(s)  (49152u + (s) * 16384u)
#define GSM_TOTAL 98304

template <int MODE>
__global__ void __launch_bounds__(256, 2)
gemm_hmma(const __half* __restrict__ Ah, const __half* __restrict__ W,
          void* __restrict__ Cout, const __half* __restrict__ Xsh,
          const float* __restrict__ Dv) {
    extern __shared__ char smem[];
    uint32_t sb = smem_u32(smem);
    const int tid = threadIdx.x, wid = tid >> 5, lane = tid & 31;
    const int wm = wid & 3, wn = wid >> 2;            // 4 x 2 warp grid
    const int m0 = blockIdx.y * 128, n0 = blockIdx.x * 128;

    // cp.async geometry: 128 rows x 8 c16 per tile; 4 per thread per tile
    const int cprow0 = tid >> 3;               // 0..31 (+ i*32)
    const int cpc16  = tid & 7;
    const uint32_t cpcol = (uint32_t)cpc16 * 16;
    const __half* Asrc = Ah + cpc16 * 8;
    const __half* Wsrc = W  + cpc16 * 8;

    // ldsm per-lane swizzled base offsets; XOR with kx (bits 5-6; disjoint)
    const uint32_t offA0 = swz128((wm * 32 + (lane & 15)) * 128 + (lane >> 4) * 16);
    const uint32_t offA1 = swz128((wm * 32 + 16 + (lane & 15)) * 128 + (lane >> 4) * 16);
    const int rowB = wn * 64 + ((lane >> 4) & 1) * 8 + (lane & 7);
    const uint32_t colB = ((lane >> 3) & 1) * 16;
    uint32_t offB[4];
    #pragma unroll
    for (int nt2 = 0; nt2 < 4; nt2++)
        offB[nt2] = swz128((rowB + nt2 * 16) * 128 + colB);

    float acc[2][8][4];
    #pragma unroll
    for (int i = 0; i < 2; i++)
        #pragma unroll
        for (int j = 0; j < 8; j++)
            #pragma unroll
            for (int q = 0; q < 4; q++) acc[i][j][q] = 0.0f;

    // prologue: issue chunks 0 and 1
    #pragma unroll
    for (int g = 0; g < 2; g++) {
        uint32_t ab = sb + STG_A(g), bb = sb + STG_B(g);
        int kc = g * CHK;
        #pragma unroll
        for (int i = 0; i < 4; i++) {
            int row = cprow0 + i * 32;
            uint32_t d = swz128(row * 128 + cpcol);
            cp16(ab + d, Asrc + (size_t)(m0 + row) * KD + kc);
            cp16(bb + d, Wsrc + (size_t)(n0 + row) * KD + kc);
        }
        CP_COMMIT();
    }

    for (int c = 0; c < NC; c++) {
        CP_WAIT1();
        __syncthreads();
        const bool pf = (c + 2 < NC);
        const int cn = c + 2;
        const uint32_t ab = sb + STG_A(cn % 3), bb = sb + STG_B(cn % 3);
        const int kc = cn * CHK;
        const uint32_t aB = sb + STG_A(c % 3), bB = sb + STG_B(c % 3);
        #pragma unroll
        for (int ks = 0; ks < 4; ks++) {
            const uint32_t kx = ks * 32;
            uint32_t afr[2][4], bfr[4][4];
            ldsm4(afr[0], aB + (offA0 ^ kx));
            ldsm4(afr[1], aB + (offA1 ^ kx));
            ldsm4(bfr[0], bB + (offB[0] ^ kx));
            ldsm4(bfr[1], bB + (offB[1] ^ kx));
            // burst 1: nt 0..3 (covers ldsm of B23 below)
            #pragma unroll
            for (int mt = 0; mt < 2; mt++)
                #pragma unroll
                for (int nt = 0; nt < 4; nt++)
                    mma_f16(acc[mt][nt], afr[mt], &bfr[nt >> 1][(nt & 1) * 2]);
            ldsm4(bfr[2], bB + (offB[2] ^ kx));
            ldsm4(bfr[3], bB + (offB[3] ^ kx));
            if (pf) {   // one A + one B cp16 per ks
                int row = cprow0 + ks * 32;
                uint32_t d = swz128(row * 128 + cpcol);
                cp16(ab + d, Asrc + (size_t)(m0 + row) * KD + kc);
                cp16(bb + d, Wsrc + (size_t)(n0 + row) * KD + kc);
            }
            // burst 2: nt 4..7
            #pragma unroll
            for (int mt = 0; mt < 2; mt++)
                #pragma unroll
                for (int nt = 4; nt < 8; nt++)
                    mma_f16(acc[mt][nt], afr[mt], &bfr[nt >> 1][(nt & 1) * 2]);
        }
        CP_COMMIT();   // one group per iteration (possibly empty)
    }
    CP_WAIT0();

    // epilogue: d0,d1 -> (row g, col 2t..2t+1); d2,d3 -> row g+8
    const int g = lane >> 2, tig = lane & 3;
    #pragma unroll
    for (int mt = 0; mt < 2; mt++) {
        #pragma unroll
        for (int nt = 0; nt < 8; nt++) {
            int r0 = m0 + wm * 32 + mt * 16 + g;
            int cc = n0 + wn * 64 + nt * 8 + tig * 2;
            if (MODE == 0) {
                __half* outh = (__half*)Cout;
                __half2 h0 = __floats2half2_rn(acc[mt][nt][0], acc[mt][nt][1]);
                __half2 h1 = __floats2half2_rn(acc[mt][nt][2], acc[mt][nt][3]);
                *(uint32_t*)(outh + (size_t)r0 * ND + cc) = *(uint32_t*)&h0;
                *(uint32_t*)(outh + (size_t)(r0 + 8) * ND + cc) = *(uint32_t*)&h1;
            } else {
                float* outf = (float*)Cout;
                float2 v0 = make_float2(acc[mt][nt][0], acc[mt][nt][1]);
                float2 v1 = make_float2(acc[mt][nt][2], acc[mt][nt][3]);
                float2 dv = *(const float2*)(Dv + cc);
                __half2 xh0 = *(const __half2*)(Xsh + (size_t)r0 * ND + cc);
                __half2 xh1 = *(const __half2*)(Xsh + (size_t)(r0 + 8) * ND + cc);
                float2 x0 = __half22float2(xh0);
                float2 x1 = __half22float2(xh1);
                v0.x = fmaf(dv.x, x0.x, v0.x); v0.y = fmaf(dv.y, x0.y, v0.y);
                v1.x = fmaf(dv.x, x1.x, v1.x); v1.y = fmaf(dv.y, x1.y, v1.y);
                *(float2*)(outf + (size_t)r0 * ND + cc) = v0;
                *(float2*)(outf + (size_t)(r0 + 8) * ND + cc) = v1;
            }
        }
    }
}

// ---------------- chunked complex scan (on scaled fp16 Bu) ---------------------
__global__ void __launch_bounds__(256) k_scan1() {
    int t = blockIdx.x * 256 + threadIdx.x;          // (b*NCH+ch)*PD + p
    int p = t & (PD - 1);
    float2 a = d_Lb[p];
    const __half2* bu = (const __half2*)d_Buh + (size_t)(t >> 8) * (CLEN * PD) + p;
    float2 s = make_float2(0.0f, 0.0f);
    #pragma unroll 4
    for (int l = 0; l < CLEN; l++) {
        float2 v = __half22float2(bu[(size_t)l * PD]);
        float sr = fmaf(a.x, s.x, fmaf(-a.y, s.y, v.x));
        float si = fmaf(a.x, s.y, fmaf(a.y, s.x, v.y));
        s.x = sr; s.y = si;
    }
    d_fin[t] = s;
}

__global__ void __launch_bounds__(256) k_scan2() {
    int t = blockIdx.x * 256 + threadIdx.x;          // b*PD + p
    int p = t & (PD - 1);
    int b = t >> 8;
    float2 A = d_Ach[p];
    float2 c = make_float2(0.0f, 0.0f);
    for (int ch = 0; ch < NCH; ch++) {
        int idx = (b * NCH + ch) * PD + p;
        d_carry[idx] = c;
        float2 f = d_fin[idx];
        float cr = fmaf(A.x, c.x, fmaf(-A.y, c.y, f.x));
        float ci = fmaf(A.x, c.y, fmaf(A.y, c.x, f.y));
        c.x = cr; c.y = ci;
    }
}

__global__ void __launch_bounds__(256) k_scan3() {
    int t = blockIdx.x * 256 + threadIdx.x;
    int p = t & (PD - 1);
    float2 a = d_Lb[p];
    float inv = d_invS[p];          // undo W1 row scaling (exact power of 2)
    size_t mbase = (size_t)(t >> 8) * CLEN;
    const __half2* bu = (const __half2*)d_Buh + mbase * PD + p;
    float2 s = d_carry[t];
    #pragma unroll 4
    for (int l = 0; l < CLEN; l++) {
        float2 v = __half22float2(bu[(size_t)l * PD]);
        float sr = fmaf(a.x, s.x, fmaf(-a.y, s.y, v.x));
        float si = fmaf(a.x, s.y, fmaf(a.y, s.x, v.y));
        s.x = sr; s.y = si;
        size_t off = (mbase + l) * ND + 2 * p;
        __half2 hv = __floats2half2_rn(sr * inv, si * inv);
        *(uint32_t*)(d_xsh + off) = *(uint32_t*)&hv;
    }
}

// ---------------- launch -------------------------------------------------------
extern "C" void kernel_launch(void* const* d_in, const int* in_sizes, int n_in,
                              void* d_out, int out_size) {
    const float* x   = (const float*)d_in[0];
    const float* Lre = (const float*)d_in[1];
    const float* Lim = (const float*)d_in[2];
    const float* Bin = (const float*)d_in[3];
    const float* Cin = (const float*)d_in[4];
    const float* Dv  = (const float*)d_in[5];
    const float* ls  = (const float*)d_in[6];
    float* out = (float*)d_out;

    __half *pxh, *pxsh, *pW1, *pW2, *pBuh;
    cudaGetSymbolAddress((void**)&pxh,  d_xh);
    cudaGetSymbolAddress((void**)&pxsh, d_xsh);
    cudaGetSymbolAddress((void**)&pW1,  d_W1t);
    cudaGetSymbolAddress((void**)&pW2,  d_W2t);
    cudaGetSymbolAddress((void**)&pBuh, d_Buh);

    cudaFuncSetAttribute(gemm_hmma<0>, cudaFuncAttributeMaxDynamicSharedMemorySize, GSM_TOTAL);
    cudaFuncSetAttribute(gemm_hmma<1>, cudaFuncAttributeMaxDynamicSharedMemorySize, GSM_TOTAL);

    k_prep1<<<1, 256>>>(Lre, Lim, ls);
    k_prep2<<<(PD * HD + 255) / 256, 256>>>(Bin, Cin);
    k_split<<<(int)(((size_t)MM * KD / 4) / 256), 256>>>(x);

    dim3 ggrid(ND / 128, MM / 128);   // (4, 256)
    gemm_hmma<0><<<ggrid, 256, GSM_TOTAL>>>(pxh, pW1, pBuh, nullptr, nullptr);

    k_scan1<<<(BSZ * NCH * PD) / 256, 256>>>();
    k_scan2<<<(BSZ * PD) / 256, 256>>>();
    k_scan3<<<(BSZ * NCH * PD) / 256, 256>>>();

    gemm_hmma<1><<<ggrid, 256, GSM_TOTAL>>>(pxsh, pW2, out, pxh, Dv);
}